// round 11
// baseline (speedup 1.0000x reference)
#include <cuda_runtime.h>

// Problem constants
#define BB   4
#define TT   2048
#define CC   1024
#define HH   16
#define DD   64
#define MROWS (BB*TT)      // 8192

// Scratch (static device globals — accessed ONLY via symbol inside kernels;
// NEVER passed as kernel arguments from host code: that passes a bogus host
// shadow pointer and trips the harness's 128 MiB memory check).
__device__ float g_q[BB*HH*TT*DD];   // [B,H,T,d]
__device__ float g_k[BB*HH*TT*DD];
__device__ float g_v[BB*HH*TT*DD];
__device__ float g_y[BB*TT*CC];      // attention output, [B,T,C]

// ---------------------------------------------------------------------------
// Kernel 1: QKV GEMM, double-buffered.  X[8192,1024] @ W[1024,3072] + bias
// -> scatter to g_q/g_k/g_v ([B,H,T,d]).
// CTA 128x128, BK=16, 256 threads, 8x8/thread, __launch_bounds__(256,1)
// (255-reg cap: staging registers cannot spill). LDG for chunk s+1 issues
// BEFORE computing chunk s; one __syncthreads per chunk.
// B half-interleaved (R8 layout): fragment reads are bank-conflict-free.
// ---------------------------------------------------------------------------
__global__ __launch_bounds__(256, 1)
void qkv_db_kernel(const float* __restrict__ Ag, const float* __restrict__ Wg,
                   const float* __restrict__ bias)
{
    __shared__ float As[2][16][132];   // k-major: As[buf][k][m]
    __shared__ float Bs[2][16][132];   // Bs[buf][k][interleaved n]

    const int tid  = threadIdx.x;
    const int ty   = tid >> 4, tx = tid & 15;
    const int row8 = ty * 8,  col8 = tx * 8;
    const int m0   = blockIdx.y * 128;
    const int n0   = blockIdx.x * 128;

    const int ar = tid >> 1;                 // A row 0..127
    const int aq = (tid & 1) * 8;            // A k-offset 0 or 8
    const int bk = tid >> 4;                 // B k row 0..15
    const int bc = tid & 15;                 // B physical chunk base

    const float* aptr = Ag + (size_t)(m0 + ar) * 1024 + aq;

    float acc[8][8];
#pragma unroll
    for (int i = 0; i < 8; i++)
#pragma unroll
        for (int j = 0; j < 8; j++) acc[i][j] = 0.f;

    float4 av0, av1, bv0, bv1;

    const int c0 = bc;                       // physical chunks bc and bc+16
    const int c1 = bc + 16;
    const int j0 = (((c0 & 15) << 1) | (c0 >> 4)) * 4;
    const int j1 = (((c1 & 15) << 1) | (c1 >> 4)) * 4;
    const float* bptr0 = Wg + (size_t)bk * 3072 + n0 + j0;
    const float* bptr1 = Wg + (size_t)bk * 3072 + n0 + j1;

#define LDG_CHUNK(S)                                                          \
    do {                                                                      \
        av0 = *(const float4*)(aptr + (S) * 16);                              \
        av1 = *(const float4*)(aptr + (S) * 16 + 4);                          \
        bv0 = *(const float4*)(bptr0 + (size_t)(S) * 16 * 3072);              \
        bv1 = *(const float4*)(bptr1 + (size_t)(S) * 16 * 3072);              \
    } while (0)

#define STS_CHUNK(BUF)                                                        \
    do {                                                                      \
        As[BUF][aq + 0][ar] = av0.x; As[BUF][aq + 1][ar] = av0.y;             \
        As[BUF][aq + 2][ar] = av0.z; As[BUF][aq + 3][ar] = av0.w;             \
        As[BUF][aq + 4][ar] = av1.x; As[BUF][aq + 5][ar] = av1.y;             \
        As[BUF][aq + 6][ar] = av1.z; As[BUF][aq + 7][ar] = av1.w;             \
        *(float4*)&Bs[BUF][bk][4 * c0] = bv0;                                 \
        *(float4*)&Bs[BUF][bk][4 * c1] = bv1;                                 \
    } while (0)

    LDG_CHUNK(0);
    STS_CHUNK(0);
    __syncthreads();

    for (int s = 0; s < 64; s++) {
        const int buf = s & 1;
        if (s < 63) LDG_CHUNK(s + 1);

#pragma unroll
        for (int kk = 0; kk < 16; kk++) {
            float a[8], b[8];
            *(float4*)&a[0] = *(float4*)&As[buf][kk][row8];
            *(float4*)&a[4] = *(float4*)&As[buf][kk][row8 + 4];
            *(float4*)&b[0] = *(float4*)&Bs[buf][kk][4 * tx];        // cols 8tx..+3
            *(float4*)&b[4] = *(float4*)&Bs[buf][kk][64 + 4 * tx];   // cols 8tx+4..+7
#pragma unroll
            for (int i = 0; i < 8; i++)
#pragma unroll
                for (int j = 0; j < 8; j++)
                    acc[i][j] = fmaf(a[i], b[j], acc[i][j]);
        }

        if (s < 63) STS_CHUNK(buf ^ 1);
        __syncthreads();
    }
#undef LDG_CHUNK
#undef STS_CHUNK

    // Epilogue: bias add + scatter to g_q/g_k/g_v
    float bvv[8];
#pragma unroll
    for (int j = 0; j < 8; j++) bvv[j] = bias[n0 + col8 + j];

    int sel = (n0 + col8) >> 10;                 // 0=q, 1=k, 2=v
    int cc0 = (n0 + col8) & 1023;
    int h   = cc0 >> 6;
    int dd  = cc0 & 63;
    float* dst = (sel == 0) ? g_q : ((sel == 1) ? g_k : g_v);
#pragma unroll
    for (int i = 0; i < 8; i++) {
        int m = m0 + row8 + i;
        int b_ = m >> 11, t = m & 2047;
        float* p = dst + ((size_t)((b_ * HH + h) * TT + t)) * DD + dd;
        *(float4*)p = make_float4(acc[i][0] + bvv[0], acc[i][1] + bvv[1],
                                  acc[i][2] + bvv[2], acc[i][3] + bvv[3]);
        *(float4*)(p + 4) = make_float4(acc[i][4] + bvv[4], acc[i][5] + bvv[5],
                                        acc[i][6] + bvv[6], acc[i][7] + bvv[7]);
    }
}

// ---------------------------------------------------------------------------
// Kernel 3: projection GEMM, double-buffered.  g_y @ W_proj + b -> out.
// Identical structure to qkv_db_kernel; A is read from the g_y SYMBOL.
// ---------------------------------------------------------------------------
__global__ __launch_bounds__(256, 1)
void proj_db_kernel(const float* __restrict__ Wg, const float* __restrict__ bias,
                    float* __restrict__ out)
{
    __shared__ float As[2][16][132];
    __shared__ float Bs[2][16][132];

    const int tid  = threadIdx.x;
    const int ty   = tid >> 4, tx = tid & 15;
    const int row8 = ty * 8,  col8 = tx * 8;
    const int m0   = blockIdx.y * 128;
    const int n0   = blockIdx.x * 128;

    const int ar = tid >> 1;
    const int aq = (tid & 1) * 8;
    const int bk = tid >> 4;
    const int bc = tid & 15;

    const float* aptr = g_y + (size_t)(m0 + ar) * 1024 + aq;   // symbol access

    float acc[8][8];
#pragma unroll
    for (int i = 0; i < 8; i++)
#pragma unroll
        for (int j = 0; j < 8; j++) acc[i][j] = 0.f;

    float4 av0, av1, bv0, bv1;

    const int c0 = bc;
    const int c1 = bc + 16;
    const int j0 = (((c0 & 15) << 1) | (c0 >> 4)) * 4;
    const int j1 = (((c1 & 15) << 1) | (c1 >> 4)) * 4;
    const float* bptr0 = Wg + (size_t)bk * CC + n0 + j0;
    const float* bptr1 = Wg + (size_t)bk * CC + n0 + j1;

#define LDG_CHUNK(S)                                                          \
    do {                                                                      \
        av0 = *(const float4*)(aptr + (S) * 16);                              \
        av1 = *(const float4*)(aptr + (S) * 16 + 4);                          \
        bv0 = *(const float4*)(bptr0 + (size_t)(S) * 16 * CC);                \
        bv1 = *(const float4*)(bptr1 + (size_t)(S) * 16 * CC);                \
    } while (0)

#define STS_CHUNK(BUF)                                                        \
    do {                                                                      \
        As[BUF][aq + 0][ar] = av0.x; As[BUF][aq + 1][ar] = av0.y;             \
        As[BUF][aq + 2][ar] = av0.z; As[BUF][aq + 3][ar] = av0.w;             \
        As[BUF][aq + 4][ar] = av1.x; As[BUF][aq + 5][ar] = av1.y;             \
        As[BUF][aq + 6][ar] = av1.z; As[BUF][aq + 7][ar] = av1.w;             \
        *(float4*)&Bs[BUF][bk][4 * c0] = bv0;                                 \
        *(float4*)&Bs[BUF][bk][4 * c1] = bv1;                                 \
    } while (0)

    LDG_CHUNK(0);
    STS_CHUNK(0);
    __syncthreads();

    for (int s = 0; s < 64; s++) {
        const int buf = s & 1;
        if (s < 63) LDG_CHUNK(s + 1);

#pragma unroll
        for (int kk = 0; kk < 16; kk++) {
            float a[8], b[8];
            *(float4*)&a[0] = *(float4*)&As[buf][kk][row8];
            *(float4*)&a[4] = *(float4*)&As[buf][kk][row8 + 4];
            *(float4*)&b[0] = *(float4*)&Bs[buf][kk][4 * tx];
            *(float4*)&b[4] = *(float4*)&Bs[buf][kk][64 + 4 * tx];
#pragma unroll
            for (int i = 0; i < 8; i++)
#pragma unroll
                for (int j = 0; j < 8; j++)
                    acc[i][j] = fmaf(a[i], b[j], acc[i][j]);
        }

        if (s < 63) STS_CHUNK(buf ^ 1);
        __syncthreads();
    }
#undef LDG_CHUNK
#undef STS_CHUNK

    float bvv[8];
#pragma unroll
    for (int j = 0; j < 8; j++) bvv[j] = bias[n0 + col8 + j];
#pragma unroll
    for (int i = 0; i < 8; i++) {
        int m = m0 + row8 + i;
        float* p = out + (size_t)m * CC + n0 + col8;
        *(float4*)p = make_float4(acc[i][0] + bvv[0], acc[i][1] + bvv[1],
                                  acc[i][2] + bvv[2], acc[i][3] + bvv[3]);
        *(float4*)(p + 4) = make_float4(acc[i][4] + bvv[4], acc[i][5] + bvv[5],
                                        acc[i][6] + bvv[6], acc[i][7] + bvv[7]);
    }
}

// ---------------------------------------------------------------------------
// Kernel 2: Flash attention (causal), fp32, online softmax.
// Math byte-identical to R1/R8. One change: heavy-first scheduling —
// q-blocks are processed in DESCENDING order of work so the 32-key-block
// CTAs launch in the first wave and the tail wave packs light CTAs.
// ---------------------------------------------------------------------------
#define ATTN_SMEM_FLOATS (64*132 + 64*68 + 128*68)   // 21504 floats = 86016 B
#define ATTN_SMEM_BYTES  (ATTN_SMEM_FLOATS * 4)

__global__ __launch_bounds__(256, 2)
void attn_kernel()
{
    extern __shared__ float smem[];
    float (*Qt)[132] = (float(*)[132])smem;                       // [d][query]
    float (*Vs)[68]  = (float(*)[68])(smem + 64 * 132);           // [key][d]
    float (*Kt)[68]  = (float(*)[68])(smem + 64 * 132 + 64 * 68); // [d][key]
    float (*Ps)[68]  = (float(*)[68])(smem + 64 * 132 + 64 * 68); // aliases Kt

    const int tid  = threadIdx.x;
    const int ty   = tid >> 4, tx = tid & 15;
    const int row8 = ty * 8;
    const int col4 = tx * 4;

    const int q0 = (gridDim.x - 1 - blockIdx.x) * 128;   // heavy-first
    const int bh = blockIdx.y;        // b*16 + h
    const float* qbase = g_q + ((size_t)bh * TT + q0) * DD;

    const float scale = 0.125f;
#pragma unroll
    for (int it = 0; it < 8; it++) {
        int idx = tid + 256 * it;
        int r   = idx >> 4;
        int dq  = (idx & 15) * 4;
        float4 v = *(const float4*)(qbase + (size_t)r * DD + dq);
        Qt[dq + 0][r] = v.x * scale; Qt[dq + 1][r] = v.y * scale;
        Qt[dq + 2][r] = v.z * scale; Qt[dq + 3][r] = v.w * scale;
    }

    float m_i[8], l_i[8], O[8][4];
#pragma unroll
    for (int i = 0; i < 8; i++) {
        m_i[i] = -1e30f; l_i[i] = 0.f;
#pragma unroll
        for (int c = 0; c < 4; c++) O[i][c] = 0.f;
    }

    const int maskStart = q0 >> 6;
    const int nblk      = maskStart + 2;

    for (int kb = 0; kb < nblk; kb++) {
        __syncthreads();

        const float* kbase = g_k + ((size_t)bh * TT + kb * 64) * DD;
        const float* vbase = g_v + ((size_t)bh * TT + kb * 64) * DD;
#pragma unroll
        for (int it = 0; it < 4; it++) {
            int idx = tid + 256 * it;
            int r   = idx >> 4;
            int dq  = (idx & 15) * 4;
            float4 kv = *(const float4*)(kbase + (size_t)r * DD + dq);
            Kt[dq + 0][r] = kv.x; Kt[dq + 1][r] = kv.y;
            Kt[dq + 2][r] = kv.z; Kt[dq + 3][r] = kv.w;
            *(float4*)&Vs[r][dq] = *(const float4*)(vbase + (size_t)r * DD + dq);
        }
        __syncthreads();

        float s[8][4];
#pragma unroll
        for (int i = 0; i < 8; i++)
#pragma unroll
            for (int j = 0; j < 4; j++) s[i][j] = 0.f;

#pragma unroll 4
        for (int dd = 0; dd < 64; dd++) {
            float4 a0 = *(float4*)&Qt[dd][row8];
            float4 a1 = *(float4*)&Qt[dd][row8 + 4];
            float4 bq = *(float4*)&Kt[dd][col4];
            float a[8] = {a0.x, a0.y, a0.z, a0.w, a1.x, a1.y, a1.z, a1.w};
            float bb[4] = {bq.x, bq.y, bq.z, bq.w};
#pragma unroll
            for (int i = 0; i < 8; i++)
#pragma unroll
                for (int j = 0; j < 4; j++)
                    s[i][j] = fmaf(a[i], bb[j], s[i][j]);
        }

        if (kb >= maskStart) {
#pragma unroll
            for (int i = 0; i < 8; i++) {
                int gq = q0 + row8 + i;
#pragma unroll
                for (int j = 0; j < 4; j++) {
                    int gk = kb * 64 + col4 + j;
                    if (gk > gq) s[i][j] = -1e30f;
                }
            }
        }

        float rmax[8], rsum[8];
#pragma unroll
        for (int i = 0; i < 8; i++) {
            float v = fmaxf(fmaxf(s[i][0], s[i][1]), fmaxf(s[i][2], s[i][3]));
#pragma unroll
            for (int o = 1; o < 16; o <<= 1)
                v = fmaxf(v, __shfl_xor_sync(0xffffffffu, v, o));
            rmax[i] = v;
        }

#pragma unroll
        for (int i = 0; i < 8; i++) {
            float mnew  = fmaxf(m_i[i], rmax[i]);
            float alpha = __expf(m_i[i] - mnew);
            m_i[i] = mnew;
            float ps = 0.f;
#pragma unroll
            for (int j = 0; j < 4; j++) {
                s[i][j] = __expf(s[i][j] - mnew);
                ps += s[i][j];
            }
#pragma unroll
            for (int o = 1; o < 16; o <<= 1)
                ps += __shfl_xor_sync(0xffffffffu, ps, o);
            rsum[i] = ps;
            l_i[i]  = l_i[i] * alpha + rsum[i];
#pragma unroll
            for (int c = 0; c < 4; c++) O[i][c] *= alpha;
        }

        __syncthreads();
#pragma unroll
        for (int i = 0; i < 8; i++)
            *(float4*)&Ps[row8 + i][col4] =
                make_float4(s[i][0], s[i][1], s[i][2], s[i][3]);
        __syncthreads();

#pragma unroll 2
        for (int j = 0; j < 64; j += 4) {
            float4 pa[8];
#pragma unroll
            for (int i = 0; i < 8; i++) pa[i] = *(float4*)&Ps[row8 + i][j];
            float4 b0 = *(float4*)&Vs[j + 0][col4];
            float4 b1 = *(float4*)&Vs[j + 1][col4];
            float4 b2 = *(float4*)&Vs[j + 2][col4];
            float4 b3 = *(float4*)&Vs[j + 3][col4];
#pragma unroll
            for (int i = 0; i < 8; i++) {
                O[i][0] = fmaf(pa[i].x, b0.x, O[i][0]);
                O[i][0] = fmaf(pa[i].y, b1.x, O[i][0]);
                O[i][0] = fmaf(pa[i].z, b2.x, O[i][0]);
                O[i][0] = fmaf(pa[i].w, b3.x, O[i][0]);
                O[i][1] = fmaf(pa[i].x, b0.y, O[i][1]);
                O[i][1] = fmaf(pa[i].y, b1.y, O[i][1]);
                O[i][1] = fmaf(pa[i].z, b2.y, O[i][1]);
                O[i][1] = fmaf(pa[i].w, b3.y, O[i][1]);
                O[i][2] = fmaf(pa[i].x, b0.z, O[i][2]);
                O[i][2] = fmaf(pa[i].y, b1.z, O[i][2]);
                O[i][2] = fmaf(pa[i].z, b2.z, O[i][2]);
                O[i][2] = fmaf(pa[i].w, b3.z, O[i][2]);
                O[i][3] = fmaf(pa[i].x, b0.w, O[i][3]);
                O[i][3] = fmaf(pa[i].y, b1.w, O[i][3]);
                O[i][3] = fmaf(pa[i].z, b2.w, O[i][3]);
                O[i][3] = fmaf(pa[i].w, b3.w, O[i][3]);
            }
        }
    }

    const int b = bh >> 4, h = bh & 15;
#pragma unroll
    for (int i = 0; i < 8; i++) {
        float inv = 1.f / l_i[i];
        int t = q0 + row8 + i;
        float* p = g_y + ((size_t)b * TT + t) * CC + h * DD + col4;
        *(float4*)p = make_float4(O[i][0] * inv, O[i][1] * inv,
                                  O[i][2] * inv, O[i][3] * inv);
    }
}

// ---------------------------------------------------------------------------
extern "C" void kernel_launch(void* const* d_in, const int* in_sizes, int n_in,
                              void* d_out, int out_size)
{
    (void)in_sizes; (void)n_in; (void)out_size;
    const float* x      = (const float*)d_in[0];
    const float* W_attn = (const float*)d_in[1];
    const float* b_attn = (const float*)d_in[2];
    const float* W_proj = (const float*)d_in[3];
    const float* b_proj = (const float*)d_in[4];
    float* out = (float*)d_out;

    cudaFuncSetAttribute(attn_kernel,
                         cudaFuncAttributeMaxDynamicSharedMemorySize,
                         ATTN_SMEM_BYTES);

    qkv_db_kernel <<<dim3(3072 / 128, MROWS / 128), 256>>>(x, W_attn, b_attn);
    attn_kernel   <<<dim3(TT / 128, BB * HH), 256, ATTN_SMEM_BYTES>>>();
    proj_db_kernel<<<dim3(CC / 128, MROWS / 128), 256>>>(W_proj, b_proj, out);
}

// round 12
// speedup vs baseline: 1.0784x; 1.0784x over previous
#include <cuda_runtime.h>
#include <cstdint>

// Problem constants
#define BB   4
#define TT   2048
#define CC   1024
#define HH   16
#define DD   64
#define MROWS (BB*TT)      // 8192

// Scratch (static device globals — accessed ONLY via symbol inside kernels;
// never passed as kernel arguments from host code).
__device__ float g_q[BB*HH*TT*DD];   // [B,H,T,d]
__device__ float g_k[BB*HH*TT*DD];
__device__ float g_v[BB*HH*TT*DD];
__device__ float g_y[BB*TT*CC];      // attention output, [B,T,C]

// ============================================================================
// Packed f32x2 helpers (PTX ISA 8.6, sm_100 family).
// Each component rounds exactly like scalar fmaf -> bit-identical results.
// ============================================================================
__device__ __forceinline__ unsigned long long pack2(float x) {
    unsigned long long r;
    asm("mov.b64 %0, {%1, %1};" : "=l"(r) : "f"(x));
    return r;
}
__device__ __forceinline__ void ffma2(unsigned long long& d,
                                      unsigned long long a,
                                      unsigned long long b) {
    asm("fma.rn.f32x2 %0, %1, %2, %0;" : "+l"(d) : "l"(a), "l"(b));
}
__device__ __forceinline__ void unpack2(unsigned long long v,
                                        float& lo, float& hi) {
    asm("mov.b64 {%0, %1}, %2;" : "=f"(lo), "=f"(hi) : "l"(v));
}

// ============================================================================
// Packed-FMA GEMM, double-buffered.  out[M,N] = A[M,1024] @ W[1024,N] + bias
// CTA 128x128, BK=16, 256 threads, 8x8/thread (as 8x4 packed pairs).
// Inner loop per kk: 4 LDS.128 + 8 mov.b64(pack a) + 32 fma.rn.f32x2
//   (vs 4 LDS.128 + 64 scalar FFMA before -> ~2x fp32 pipe utilization).
// b-pairs come directly from the float4 fragment loads (consecutive cols).
// __launch_bounds__(256,1): 255-reg cap, no spill.
// ============================================================================
__global__ __launch_bounds__(256, 1)
void qkv_p2_kernel(const float* __restrict__ Ag, const float* __restrict__ Wg,
                   const float* __restrict__ bias)
{
    __shared__ float As[2][16][132];   // k-major: As[buf][k][m]
    __shared__ float Bs[2][16][132];   // Bs[buf][k][interleaved n]

    const int tid  = threadIdx.x;
    const int ty   = tid >> 4, tx = tid & 15;
    const int row8 = ty * 8,  col8 = tx * 8;
    const int m0   = blockIdx.y * 128;
    const int n0   = blockIdx.x * 128;

    const int ar = tid >> 1;                 // A row 0..127
    const int aq = (tid & 1) * 8;            // A k-offset 0 or 8
    const int bk = tid >> 4;                 // B k row 0..15
    const int bc = tid & 15;                 // B physical chunk base

    const float* aptr = Ag + (size_t)(m0 + ar) * 1024 + aq;

    unsigned long long acc2[8][4];           // [row][col-pair]
#pragma unroll
    for (int i = 0; i < 8; i++)
#pragma unroll
        for (int j = 0; j < 4; j++) acc2[i][j] = 0ull;

    float4 av0, av1, bv0, bv1;

    const int c0 = bc, c1 = bc + 16;
    const int j0 = (((c0 & 15) << 1) | (c0 >> 4)) * 4;
    const int j1 = (((c1 & 15) << 1) | (c1 >> 4)) * 4;
    const float* bptr0 = Wg + (size_t)bk * 3072 + n0 + j0;
    const float* bptr1 = Wg + (size_t)bk * 3072 + n0 + j1;

#define LDG_CHUNK(S)                                                          \
    do {                                                                      \
        av0 = *(const float4*)(aptr + (S) * 16);                              \
        av1 = *(const float4*)(aptr + (S) * 16 + 4);                          \
        bv0 = *(const float4*)(bptr0 + (size_t)(S) * 16 * 3072);              \
        bv1 = *(const float4*)(bptr1 + (size_t)(S) * 16 * 3072);              \
    } while (0)

#define STS_CHUNK(BUF)                                                        \
    do {                                                                      \
        As[BUF][aq + 0][ar] = av0.x; As[BUF][aq + 1][ar] = av0.y;             \
        As[BUF][aq + 2][ar] = av0.z; As[BUF][aq + 3][ar] = av0.w;             \
        As[BUF][aq + 4][ar] = av1.x; As[BUF][aq + 5][ar] = av1.y;             \
        As[BUF][aq + 6][ar] = av1.z; As[BUF][aq + 7][ar] = av1.w;             \
        *(float4*)&Bs[BUF][bk][4 * c0] = bv0;                                 \
        *(float4*)&Bs[BUF][bk][4 * c1] = bv1;                                 \
    } while (0)

    LDG_CHUNK(0);
    STS_CHUNK(0);
    __syncthreads();

    for (int s = 0; s < 64; s++) {
        const int buf = s & 1;
        if (s < 63) LDG_CHUNK(s + 1);

#pragma unroll
        for (int kk = 0; kk < 16; kk++) {
            float a[8];
            *(float4*)&a[0] = *(float4*)&As[buf][kk][row8];
            *(float4*)&a[4] = *(float4*)&As[buf][kk][row8 + 4];
            float4 b0 = *(float4*)&Bs[buf][kk][4 * tx];        // cols 8tx..+3
            float4 b1 = *(float4*)&Bs[buf][kk][64 + 4 * tx];   // cols 8tx+4..+7
            unsigned long long bp[4];
            bp[0] = ((const unsigned long long*)&b0)[0];       // (c0,c1)
            bp[1] = ((const unsigned long long*)&b0)[1];       // (c2,c3)
            bp[2] = ((const unsigned long long*)&b1)[0];       // (c4,c5)
            bp[3] = ((const unsigned long long*)&b1)[1];       // (c6,c7)
#pragma unroll
            for (int i = 0; i < 8; i++) {
                unsigned long long ap = pack2(a[i]);
                ffma2(acc2[i][0], ap, bp[0]);
                ffma2(acc2[i][1], ap, bp[1]);
                ffma2(acc2[i][2], ap, bp[2]);
                ffma2(acc2[i][3], ap, bp[3]);
            }
        }

        if (s < 63) STS_CHUNK(buf ^ 1);
        __syncthreads();
    }
#undef LDG_CHUNK
#undef STS_CHUNK

    // Epilogue: unpack, bias add, scatter to g_q/g_k/g_v
    float bvv[8];
#pragma unroll
    for (int j = 0; j < 8; j++) bvv[j] = bias[n0 + col8 + j];

    int sel = (n0 + col8) >> 10;                 // 0=q, 1=k, 2=v
    int cc0 = (n0 + col8) & 1023;
    int h   = cc0 >> 6;
    int dd  = cc0 & 63;
    float* dst = (sel == 0) ? g_q : ((sel == 1) ? g_k : g_v);
#pragma unroll
    for (int i = 0; i < 8; i++) {
        float acc[8];
#pragma unroll
        for (int jp = 0; jp < 4; jp++)
            unpack2(acc2[i][jp], acc[2 * jp], acc[2 * jp + 1]);
        int m = m0 + row8 + i;
        int b_ = m >> 11, t = m & 2047;
        float* p = dst + ((size_t)((b_ * HH + h) * TT + t)) * DD + dd;
        *(float4*)p = make_float4(acc[0] + bvv[0], acc[1] + bvv[1],
                                  acc[2] + bvv[2], acc[3] + bvv[3]);
        *(float4*)(p + 4) = make_float4(acc[4] + bvv[4], acc[5] + bvv[5],
                                        acc[6] + bvv[6], acc[7] + bvv[7]);
    }
}

// ---------------------------------------------------------------------------
// Projection GEMM, identical packed structure; A read from the g_y SYMBOL.
// ---------------------------------------------------------------------------
__global__ __launch_bounds__(256, 1)
void proj_p2_kernel(const float* __restrict__ Wg, const float* __restrict__ bias,
                    float* __restrict__ out)
{
    __shared__ float As[2][16][132];
    __shared__ float Bs[2][16][132];

    const int tid  = threadIdx.x;
    const int ty   = tid >> 4, tx = tid & 15;
    const int row8 = ty * 8,  col8 = tx * 8;
    const int m0   = blockIdx.y * 128;
    const int n0   = blockIdx.x * 128;

    const int ar = tid >> 1;
    const int aq = (tid & 1) * 8;
    const int bk = tid >> 4;
    const int bc = tid & 15;

    const float* aptr = g_y + (size_t)(m0 + ar) * 1024 + aq;   // symbol access

    unsigned long long acc2[8][4];
#pragma unroll
    for (int i = 0; i < 8; i++)
#pragma unroll
        for (int j = 0; j < 4; j++) acc2[i][j] = 0ull;

    float4 av0, av1, bv0, bv1;

    const int c0 = bc, c1 = bc + 16;
    const int j0 = (((c0 & 15) << 1) | (c0 >> 4)) * 4;
    const int j1 = (((c1 & 15) << 1) | (c1 >> 4)) * 4;
    const float* bptr0 = Wg + (size_t)bk * CC + n0 + j0;
    const float* bptr1 = Wg + (size_t)bk * CC + n0 + j1;

#define LDG_CHUNK(S)                                                          \
    do {                                                                      \
        av0 = *(const float4*)(aptr + (S) * 16);                              \
        av1 = *(const float4*)(aptr + (S) * 16 + 4);                          \
        bv0 = *(const float4*)(bptr0 + (size_t)(S) * 16 * CC);                \
        bv1 = *(const float4*)(bptr1 + (size_t)(S) * 16 * CC);                \
    } while (0)

#define STS_CHUNK(BUF)                                                        \
    do {                                                                      \
        As[BUF][aq + 0][ar] = av0.x; As[BUF][aq + 1][ar] = av0.y;             \
        As[BUF][aq + 2][ar] = av0.z; As[BUF][aq + 3][ar] = av0.w;             \
        As[BUF][aq + 4][ar] = av1.x; As[BUF][aq + 5][ar] = av1.y;             \
        As[BUF][aq + 6][ar] = av1.z; As[BUF][aq + 7][ar] = av1.w;             \
        *(float4*)&Bs[BUF][bk][4 * c0] = bv0;                                 \
        *(float4*)&Bs[BUF][bk][4 * c1] = bv1;                                 \
    } while (0)

    LDG_CHUNK(0);
    STS_CHUNK(0);
    __syncthreads();

    for (int s = 0; s < 64; s++) {
        const int buf = s & 1;
        if (s < 63) LDG_CHUNK(s + 1);

#pragma unroll
        for (int kk = 0; kk < 16; kk++) {
            float a[8];
            *(float4*)&a[0] = *(float4*)&As[buf][kk][row8];
            *(float4*)&a[4] = *(float4*)&As[buf][kk][row8 + 4];
            float4 b0 = *(float4*)&Bs[buf][kk][4 * tx];
            float4 b1 = *(float4*)&Bs[buf][kk][64 + 4 * tx];
            unsigned long long bp[4];
            bp[0] = ((const unsigned long long*)&b0)[0];
            bp[1] = ((const unsigned long long*)&b0)[1];
            bp[2] = ((const unsigned long long*)&b1)[0];
            bp[3] = ((const unsigned long long*)&b1)[1];
#pragma unroll
            for (int i = 0; i < 8; i++) {
                unsigned long long ap = pack2(a[i]);
                ffma2(acc2[i][0], ap, bp[0]);
                ffma2(acc2[i][1], ap, bp[1]);
                ffma2(acc2[i][2], ap, bp[2]);
                ffma2(acc2[i][3], ap, bp[3]);
            }
        }

        if (s < 63) STS_CHUNK(buf ^ 1);
        __syncthreads();
    }
#undef LDG_CHUNK
#undef STS_CHUNK

    float bvv[8];
#pragma unroll
    for (int j = 0; j < 8; j++) bvv[j] = bias[n0 + col8 + j];
#pragma unroll
    for (int i = 0; i < 8; i++) {
        float acc[8];
#pragma unroll
        for (int jp = 0; jp < 4; jp++)
            unpack2(acc2[i][jp], acc[2 * jp], acc[2 * jp + 1]);
        int m = m0 + row8 + i;
        float* p = out + (size_t)m * CC + n0 + col8;
        *(float4*)p = make_float4(acc[0] + bvv[0], acc[1] + bvv[1],
                                  acc[2] + bvv[2], acc[3] + bvv[3]);
        *(float4*)(p + 4) = make_float4(acc[4] + bvv[4], acc[5] + bvv[5],
                                        acc[6] + bvv[6], acc[7] + bvv[7]);
    }
}

// ---------------------------------------------------------------------------
// Kernel 2: Flash attention (causal), fp32, online softmax.
// BYTE-IDENTICAL to the Round-8 pass (the best-known config; no heavy-first).
// ---------------------------------------------------------------------------
#define ATTN_SMEM_FLOATS (64*132 + 64*68 + 128*68)   // 21504 floats = 86016 B
#define ATTN_SMEM_BYTES  (ATTN_SMEM_FLOATS * 4)

__global__ __launch_bounds__(256, 2)
void attn_kernel()
{
    extern __shared__ float smem[];
    float (*Qt)[132] = (float(*)[132])smem;                       // [d][query]
    float (*Vs)[68]  = (float(*)[68])(smem + 64 * 132);           // [key][d]
    float (*Kt)[68]  = (float(*)[68])(smem + 64 * 132 + 64 * 68); // [d][key]
    float (*Ps)[68]  = (float(*)[68])(smem + 64 * 132 + 64 * 68); // aliases Kt

    const int tid  = threadIdx.x;
    const int ty   = tid >> 4, tx = tid & 15;
    const int row8 = ty * 8;
    const int col4 = tx * 4;

    const int q0 = blockIdx.x * 128;
    const int bh = blockIdx.y;        // b*16 + h
    const float* qbase = g_q + ((size_t)bh * TT + q0) * DD;

    const float scale = 0.125f;
#pragma unroll
    for (int it = 0; it < 8; it++) {
        int idx = tid + 256 * it;
        int r   = idx >> 4;
        int dq  = (idx & 15) * 4;
        float4 v = *(const float4*)(qbase + (size_t)r * DD + dq);
        Qt[dq + 0][r] = v.x * scale; Qt[dq + 1][r] = v.y * scale;
        Qt[dq + 2][r] = v.z * scale; Qt[dq + 3][r] = v.w * scale;
    }

    float m_i[8], l_i[8], O[8][4];
#pragma unroll
    for (int i = 0; i < 8; i++) {
        m_i[i] = -1e30f; l_i[i] = 0.f;
#pragma unroll
        for (int c = 0; c < 4; c++) O[i][c] = 0.f;
    }

    const int maskStart = q0 >> 6;
    const int nblk      = maskStart + 2;

    for (int kb = 0; kb < nblk; kb++) {
        __syncthreads();

        const float* kbase = g_k + ((size_t)bh * TT + kb * 64) * DD;
        const float* vbase = g_v + ((size_t)bh * TT + kb * 64) * DD;
#pragma unroll
        for (int it = 0; it < 4; it++) {
            int idx = tid + 256 * it;
            int r   = idx >> 4;
            int dq  = (idx & 15) * 4;
            float4 kv = *(const float4*)(kbase + (size_t)r * DD + dq);
            Kt[dq + 0][r] = kv.x; Kt[dq + 1][r] = kv.y;
            Kt[dq + 2][r] = kv.z; Kt[dq + 3][r] = kv.w;
            *(float4*)&Vs[r][dq] = *(const float4*)(vbase + (size_t)r * DD + dq);
        }
        __syncthreads();

        float s[8][4];
#pragma unroll
        for (int i = 0; i < 8; i++)
#pragma unroll
            for (int j = 0; j < 4; j++) s[i][j] = 0.f;

#pragma unroll 4
        for (int dd = 0; dd < 64; dd++) {
            float4 a0 = *(float4*)&Qt[dd][row8];
            float4 a1 = *(float4*)&Qt[dd][row8 + 4];
            float4 bq = *(float4*)&Kt[dd][col4];
            float a[8] = {a0.x, a0.y, a0.z, a0.w, a1.x, a1.y, a1.z, a1.w};
            float bb[4] = {bq.x, bq.y, bq.z, bq.w};
#pragma unroll
            for (int i = 0; i < 8; i++)
#pragma unroll
                for (int j = 0; j < 4; j++)
                    s[i][j] = fmaf(a[i], bb[j], s[i][j]);
        }

        if (kb >= maskStart) {
#pragma unroll
            for (int i = 0; i < 8; i++) {
                int gq = q0 + row8 + i;
#pragma unroll
                for (int j = 0; j < 4; j++) {
                    int gk = kb * 64 + col4 + j;
                    if (gk > gq) s[i][j] = -1e30f;
                }
            }
        }

        float rmax[8], rsum[8];
#pragma unroll
        for (int i = 0; i < 8; i++) {
            float v = fmaxf(fmaxf(s[i][0], s[i][1]), fmaxf(s[i][2], s[i][3]));
#pragma unroll
            for (int o = 1; o < 16; o <<= 1)
                v = fmaxf(v, __shfl_xor_sync(0xffffffffu, v, o));
            rmax[i] = v;
        }

#pragma unroll
        for (int i = 0; i < 8; i++) {
            float mnew  = fmaxf(m_i[i], rmax[i]);
            float alpha = __expf(m_i[i] - mnew);
            m_i[i] = mnew;
            float ps = 0.f;
#pragma unroll
            for (int j = 0; j < 4; j++) {
                s[i][j] = __expf(s[i][j] - mnew);
                ps += s[i][j];
            }
#pragma unroll
            for (int o = 1; o < 16; o <<= 1)
                ps += __shfl_xor_sync(0xffffffffu, ps, o);
            rsum[i] = ps;
            l_i[i]  = l_i[i] * alpha + rsum[i];
#pragma unroll
            for (int c = 0; c < 4; c++) O[i][c] *= alpha;
        }

        __syncthreads();
#pragma unroll
        for (int i = 0; i < 8; i++)
            *(float4*)&Ps[row8 + i][col4] =
                make_float4(s[i][0], s[i][1], s[i][2], s[i][3]);
        __syncthreads();

#pragma unroll 2
        for (int j = 0; j < 64; j += 4) {
            float4 pa[8];
#pragma unroll
            for (int i = 0; i < 8; i++) pa[i] = *(float4*)&Ps[row8 + i][j];
            float4 b0 = *(float4*)&Vs[j + 0][col4];
            float4 b1 = *(float4*)&Vs[j + 1][col4];
            float4 b2 = *(float4*)&Vs[j + 2][col4];
            float4 b3 = *(float4*)&Vs[j + 3][col4];
#pragma unroll
            for (int i = 0; i < 8; i++) {
                O[i][0] = fmaf(pa[i].x, b0.x, O[i][0]);
                O[i][0] = fmaf(pa[i].y, b1.x, O[i][0]);
                O[i][0] = fmaf(pa[i].z, b2.x, O[i][0]);
                O[i][0] = fmaf(pa[i].w, b3.x, O[i][0]);
                O[i][1] = fmaf(pa[i].x, b0.y, O[i][1]);
                O[i][1] = fmaf(pa[i].y, b1.y, O[i][1]);
                O[i][1] = fmaf(pa[i].z, b2.y, O[i][1]);
                O[i][1] = fmaf(pa[i].w, b3.y, O[i][1]);
                O[i][2] = fmaf(pa[i].x, b0.z, O[i][2]);
                O[i][2] = fmaf(pa[i].y, b1.z, O[i][2]);
                O[i][2] = fmaf(pa[i].z, b2.z, O[i][2]);
                O[i][2] = fmaf(pa[i].w, b3.z, O[i][2]);
                O[i][3] = fmaf(pa[i].x, b0.w, O[i][3]);
                O[i][3] = fmaf(pa[i].y, b1.w, O[i][3]);
                O[i][3] = fmaf(pa[i].z, b2.w, O[i][3]);
                O[i][3] = fmaf(pa[i].w, b3.w, O[i][3]);
            }
        }
    }

    const int b = bh >> 4, h = bh & 15;
#pragma unroll
    for (int i = 0; i < 8; i++) {
        float inv = 1.f / l_i[i];
        int t = q0 + row8 + i;
        float* p = g_y + ((size_t)b * TT + t) * CC + h * DD + col4;
        *(float4*)p = make_float4(O[i][0] * inv, O[i][1] * inv,
                                  O[i][2] * inv, O[i][3] * inv);
    }
}

// ---------------------------------------------------------------------------
extern "C" void kernel_launch(void* const* d_in, const int* in_sizes, int n_in,
                              void* d_out, int out_size)
{
    (void)in_sizes; (void)n_in; (void)out_size;
    const float* x      = (const float*)d_in[0];
    const float* W_attn = (const float*)d_in[1];
    const float* b_attn = (const float*)d_in[2];
    const float* W_proj = (const float*)d_in[3];
    const float* b_proj = (const float*)d_in[4];
    float* out = (float*)d_out;

    cudaFuncSetAttribute(attn_kernel,
                         cudaFuncAttributeMaxDynamicSharedMemorySize,
                         ATTN_SMEM_BYTES);

    qkv_p2_kernel <<<dim3(3072 / 128, MROWS / 128), 256>>>(x, W_attn, b_attn);
    attn_kernel   <<<dim3(TT / 128, BB * HH), 256, ATTN_SMEM_BYTES>>>();
    proj_p2_kernel<<<dim3(CC / 128, MROWS / 128), 256>>>(W_proj, b_proj, out);
}

// round 13
// speedup vs baseline: 1.1005x; 1.0205x over previous
#include <cuda_runtime.h>
#include <cstdint>

// Problem constants
#define BB   4
#define TT   2048
#define CC   1024
#define HH   16
#define DD   64
#define MROWS (BB*TT)      // 8192

// Scratch (static device globals — accessed ONLY via symbol inside kernels;
// never passed as kernel arguments from host code).
__device__ float g_q[BB*HH*TT*DD];   // [B,H,T,d]
__device__ float g_k[BB*HH*TT*DD];
__device__ float g_v[BB*HH*TT*DD];
__device__ float g_y[BB*TT*CC];      // attention output, [B,T,C]

// ============================================================================
// Packed f32x2 helpers (PTX ISA 8.6, sm_100 family).
// Per-component rounding identical to scalar fmaf -> bit-identical results.
// ============================================================================
typedef unsigned long long u64;

__device__ __forceinline__ u64 pack2(float x) {
    u64 r;
    asm("mov.b64 %0, {%1, %1};" : "=l"(r) : "f"(x));
    return r;
}
__device__ __forceinline__ void ffma2(u64& d, u64 a, u64 b) {
    asm("fma.rn.f32x2 %0, %1, %2, %0;" : "+l"(d) : "l"(a), "l"(b));
}
__device__ __forceinline__ void fmul2(u64& d, u64 a) {
    asm("mul.rn.f32x2 %0, %0, %1;" : "+l"(d) : "l"(a));
}
__device__ __forceinline__ void unpack2(u64 v, float& lo, float& hi) {
    asm("mov.b64 {%0, %1}, %2;" : "=f"(lo), "=f"(hi) : "l"(v));
}

// ============================================================================
// Packed-FMA GEMM, double-buffered (UNCHANGED from Round-12 winner).
// ============================================================================
__global__ __launch_bounds__(256, 1)
void qkv_p2_kernel(const float* __restrict__ Ag, const float* __restrict__ Wg,
                   const float* __restrict__ bias)
{
    __shared__ float As[2][16][132];
    __shared__ float Bs[2][16][132];

    const int tid  = threadIdx.x;
    const int ty   = tid >> 4, tx = tid & 15;
    const int row8 = ty * 8,  col8 = tx * 8;
    const int m0   = blockIdx.y * 128;
    const int n0   = blockIdx.x * 128;

    const int ar = tid >> 1;
    const int aq = (tid & 1) * 8;
    const int bk = tid >> 4;
    const int bc = tid & 15;

    const float* aptr = Ag + (size_t)(m0 + ar) * 1024 + aq;

    u64 acc2[8][4];
#pragma unroll
    for (int i = 0; i < 8; i++)
#pragma unroll
        for (int j = 0; j < 4; j++) acc2[i][j] = 0ull;

    float4 av0, av1, bv0, bv1;

    const int c0 = bc, c1 = bc + 16;
    const int j0 = (((c0 & 15) << 1) | (c0 >> 4)) * 4;
    const int j1 = (((c1 & 15) << 1) | (c1 >> 4)) * 4;
    const float* bptr0 = Wg + (size_t)bk * 3072 + n0 + j0;
    const float* bptr1 = Wg + (size_t)bk * 3072 + n0 + j1;

#define LDG_CHUNK(S)                                                          \
    do {                                                                      \
        av0 = *(const float4*)(aptr + (S) * 16);                              \
        av1 = *(const float4*)(aptr + (S) * 16 + 4);                          \
        bv0 = *(const float4*)(bptr0 + (size_t)(S) * 16 * 3072);              \
        bv1 = *(const float4*)(bptr1 + (size_t)(S) * 16 * 3072);              \
    } while (0)

#define STS_CHUNK(BUF)                                                        \
    do {                                                                      \
        As[BUF][aq + 0][ar] = av0.x; As[BUF][aq + 1][ar] = av0.y;             \
        As[BUF][aq + 2][ar] = av0.z; As[BUF][aq + 3][ar] = av0.w;             \
        As[BUF][aq + 4][ar] = av1.x; As[BUF][aq + 5][ar] = av1.y;             \
        As[BUF][aq + 6][ar] = av1.z; As[BUF][aq + 7][ar] = av1.w;             \
        *(float4*)&Bs[BUF][bk][4 * c0] = bv0;                                 \
        *(float4*)&Bs[BUF][bk][4 * c1] = bv1;                                 \
    } while (0)

    LDG_CHUNK(0);
    STS_CHUNK(0);
    __syncthreads();

    for (int s = 0; s < 64; s++) {
        const int buf = s & 1;
        if (s < 63) LDG_CHUNK(s + 1);

#pragma unroll
        for (int kk = 0; kk < 16; kk++) {
            float a[8];
            *(float4*)&a[0] = *(float4*)&As[buf][kk][row8];
            *(float4*)&a[4] = *(float4*)&As[buf][kk][row8 + 4];
            float4 b0 = *(float4*)&Bs[buf][kk][4 * tx];
            float4 b1 = *(float4*)&Bs[buf][kk][64 + 4 * tx];
            u64 bp[4];
            bp[0] = ((const u64*)&b0)[0];
            bp[1] = ((const u64*)&b0)[1];
            bp[2] = ((const u64*)&b1)[0];
            bp[3] = ((const u64*)&b1)[1];
#pragma unroll
            for (int i = 0; i < 8; i++) {
                u64 ap = pack2(a[i]);
                ffma2(acc2[i][0], ap, bp[0]);
                ffma2(acc2[i][1], ap, bp[1]);
                ffma2(acc2[i][2], ap, bp[2]);
                ffma2(acc2[i][3], ap, bp[3]);
            }
        }

        if (s < 63) STS_CHUNK(buf ^ 1);
        __syncthreads();
    }
#undef LDG_CHUNK
#undef STS_CHUNK

    float bvv[8];
#pragma unroll
    for (int j = 0; j < 8; j++) bvv[j] = bias[n0 + col8 + j];

    int sel = (n0 + col8) >> 10;
    int cc0 = (n0 + col8) & 1023;
    int h   = cc0 >> 6;
    int dd  = cc0 & 63;
    float* dst = (sel == 0) ? g_q : ((sel == 1) ? g_k : g_v);
#pragma unroll
    for (int i = 0; i < 8; i++) {
        float acc[8];
#pragma unroll
        for (int jp = 0; jp < 4; jp++)
            unpack2(acc2[i][jp], acc[2 * jp], acc[2 * jp + 1]);
        int m = m0 + row8 + i;
        int b_ = m >> 11, t = m & 2047;
        float* p = dst + ((size_t)((b_ * HH + h) * TT + t)) * DD + dd;
        *(float4*)p = make_float4(acc[0] + bvv[0], acc[1] + bvv[1],
                                  acc[2] + bvv[2], acc[3] + bvv[3]);
        *(float4*)(p + 4) = make_float4(acc[4] + bvv[4], acc[5] + bvv[5],
                                        acc[6] + bvv[6], acc[7] + bvv[7]);
    }
}

__global__ __launch_bounds__(256, 1)
void proj_p2_kernel(const float* __restrict__ Wg, const float* __restrict__ bias,
                    float* __restrict__ out)
{
    __shared__ float As[2][16][132];
    __shared__ float Bs[2][16][132];

    const int tid  = threadIdx.x;
    const int ty   = tid >> 4, tx = tid & 15;
    const int row8 = ty * 8,  col8 = tx * 8;
    const int m0   = blockIdx.y * 128;
    const int n0   = blockIdx.x * 128;

    const int ar = tid >> 1;
    const int aq = (tid & 1) * 8;
    const int bk = tid >> 4;
    const int bc = tid & 15;

    const float* aptr = g_y + (size_t)(m0 + ar) * 1024 + aq;   // symbol access

    u64 acc2[8][4];
#pragma unroll
    for (int i = 0; i < 8; i++)
#pragma unroll
        for (int j = 0; j < 4; j++) acc2[i][j] = 0ull;

    float4 av0, av1, bv0, bv1;

    const int c0 = bc, c1 = bc + 16;
    const int j0 = (((c0 & 15) << 1) | (c0 >> 4)) * 4;
    const int j1 = (((c1 & 15) << 1) | (c1 >> 4)) * 4;
    const float* bptr0 = Wg + (size_t)bk * CC + n0 + j0;
    const float* bptr1 = Wg + (size_t)bk * CC + n0 + j1;

#define LDG_CHUNK(S)                                                          \
    do {                                                                      \
        av0 = *(const float4*)(aptr + (S) * 16);                              \
        av1 = *(const float4*)(aptr + (S) * 16 + 4);                          \
        bv0 = *(const float4*)(bptr0 + (size_t)(S) * 16 * CC);                \
        bv1 = *(const float4*)(bptr1 + (size_t)(S) * 16 * CC);                \
    } while (0)

#define STS_CHUNK(BUF)                                                        \
    do {                                                                      \
        As[BUF][aq + 0][ar] = av0.x; As[BUF][aq + 1][ar] = av0.y;             \
        As[BUF][aq + 2][ar] = av0.z; As[BUF][aq + 3][ar] = av0.w;             \
        As[BUF][aq + 4][ar] = av1.x; As[BUF][aq + 5][ar] = av1.y;             \
        As[BUF][aq + 6][ar] = av1.z; As[BUF][aq + 7][ar] = av1.w;             \
        *(float4*)&Bs[BUF][bk][4 * c0] = bv0;                                 \
        *(float4*)&Bs[BUF][bk][4 * c1] = bv1;                                 \
    } while (0)

    LDG_CHUNK(0);
    STS_CHUNK(0);
    __syncthreads();

    for (int s = 0; s < 64; s++) {
        const int buf = s & 1;
        if (s < 63) LDG_CHUNK(s + 1);

#pragma unroll
        for (int kk = 0; kk < 16; kk++) {
            float a[8];
            *(float4*)&a[0] = *(float4*)&As[buf][kk][row8];
            *(float4*)&a[4] = *(float4*)&As[buf][kk][row8 + 4];
            float4 b0 = *(float4*)&Bs[buf][kk][4 * tx];
            float4 b1 = *(float4*)&Bs[buf][kk][64 + 4 * tx];
            u64 bp[4];
            bp[0] = ((const u64*)&b0)[0];
            bp[1] = ((const u64*)&b0)[1];
            bp[2] = ((const u64*)&b1)[0];
            bp[3] = ((const u64*)&b1)[1];
#pragma unroll
            for (int i = 0; i < 8; i++) {
                u64 ap = pack2(a[i]);
                ffma2(acc2[i][0], ap, bp[0]);
                ffma2(acc2[i][1], ap, bp[1]);
                ffma2(acc2[i][2], ap, bp[2]);
                ffma2(acc2[i][3], ap, bp[3]);
            }
        }

        if (s < 63) STS_CHUNK(buf ^ 1);
        __syncthreads();
    }
#undef LDG_CHUNK
#undef STS_CHUNK

    float bvv[8];
#pragma unroll
    for (int j = 0; j < 8; j++) bvv[j] = bias[n0 + col8 + j];
#pragma unroll
    for (int i = 0; i < 8; i++) {
        float acc[8];
#pragma unroll
        for (int jp = 0; jp < 4; jp++)
            unpack2(acc2[i][jp], acc[2 * jp], acc[2 * jp + 1]);
        int m = m0 + row8 + i;
        float* p = out + (size_t)m * CC + n0 + col8;
        *(float4*)p = make_float4(acc[0] + bvv[0], acc[1] + bvv[1],
                                  acc[2] + bvv[2], acc[3] + bvv[3]);
        *(float4*)(p + 4) = make_float4(acc[4] + bvv[4], acc[5] + bvv[5],
                                        acc[6] + bvv[6], acc[7] + bvv[7]);
    }
}

// ---------------------------------------------------------------------------
// Kernel 2: Flash attention (causal), fp32, online softmax — now with packed
// f32x2 FMA in both the S=QK^T and O+=P@V loops (per-component IEEE-identical
// to the scalar version; softmax/masking unchanged and scalar).
// ---------------------------------------------------------------------------
#define ATTN_SMEM_FLOATS (64*132 + 64*68 + 128*68)   // 86016 B
#define ATTN_SMEM_BYTES  (ATTN_SMEM_FLOATS * 4)

__global__ __launch_bounds__(256, 2)
void attn_kernel()
{
    extern __shared__ float smem[];
    float (*Qt)[132] = (float(*)[132])smem;                       // [d][query]
    float (*Vs)[68]  = (float(*)[68])(smem + 64 * 132);           // [key][d]
    float (*Kt)[68]  = (float(*)[68])(smem + 64 * 132 + 64 * 68); // [d][key]
    float (*Ps)[68]  = (float(*)[68])(smem + 64 * 132 + 64 * 68); // aliases Kt

    const int tid  = threadIdx.x;
    const int ty   = tid >> 4, tx = tid & 15;
    const int row8 = ty * 8;
    const int col4 = tx * 4;

    const int q0 = blockIdx.x * 128;
    const int bh = blockIdx.y;        // b*16 + h
    const float* qbase = g_q + ((size_t)bh * TT + q0) * DD;

    const float scale = 0.125f;
#pragma unroll
    for (int it = 0; it < 8; it++) {
        int idx = tid + 256 * it;
        int r   = idx >> 4;
        int dq  = (idx & 15) * 4;
        float4 v = *(const float4*)(qbase + (size_t)r * DD + dq);
        Qt[dq + 0][r] = v.x * scale; Qt[dq + 1][r] = v.y * scale;
        Qt[dq + 2][r] = v.z * scale; Qt[dq + 3][r] = v.w * scale;
    }

    float m_i[8], l_i[8];
    u64 O2[8][2];                      // O pairs: (c0,c1),(c2,c3)
#pragma unroll
    for (int i = 0; i < 8; i++) {
        m_i[i] = -1e30f; l_i[i] = 0.f;
        O2[i][0] = 0ull; O2[i][1] = 0ull;
    }

    const int maskStart = q0 >> 6;
    const int nblk      = maskStart + 2;

    for (int kb = 0; kb < nblk; kb++) {
        __syncthreads();

        const float* kbase = g_k + ((size_t)bh * TT + kb * 64) * DD;
        const float* vbase = g_v + ((size_t)bh * TT + kb * 64) * DD;
#pragma unroll
        for (int it = 0; it < 4; it++) {
            int idx = tid + 256 * it;
            int r   = idx >> 4;
            int dq  = (idx & 15) * 4;
            float4 kv = *(const float4*)(kbase + (size_t)r * DD + dq);
            Kt[dq + 0][r] = kv.x; Kt[dq + 1][r] = kv.y;
            Kt[dq + 2][r] = kv.z; Kt[dq + 3][r] = kv.w;
            *(float4*)&Vs[r][dq] = *(const float4*)(vbase + (size_t)r * DD + dq);
        }
        __syncthreads();

        // ---- S = Q K^T, packed: per dd 8 packs + 16 FFMA2 (was 32 FFMA) ----
        u64 s2[8][2];
#pragma unroll
        for (int i = 0; i < 8; i++) { s2[i][0] = 0ull; s2[i][1] = 0ull; }

#pragma unroll 4
        for (int dd = 0; dd < 64; dd++) {
            float4 a0 = *(float4*)&Qt[dd][row8];
            float4 a1 = *(float4*)&Qt[dd][row8 + 4];
            float4 bq = *(float4*)&Kt[dd][col4];
            u64 bp0 = ((const u64*)&bq)[0];    // (k0,k1)
            u64 bp1 = ((const u64*)&bq)[1];    // (k2,k3)
            float a[8] = {a0.x, a0.y, a0.z, a0.w, a1.x, a1.y, a1.z, a1.w};
#pragma unroll
            for (int i = 0; i < 8; i++) {
                u64 ap = pack2(a[i]);
                ffma2(s2[i][0], ap, bp0);
                ffma2(s2[i][1], ap, bp1);
            }
        }

        // Unpack scores for masking + softmax (scalar, unchanged math)
        float s[8][4];
#pragma unroll
        for (int i = 0; i < 8; i++) {
            unpack2(s2[i][0], s[i][0], s[i][1]);
            unpack2(s2[i][1], s[i][2], s[i][3]);
        }

        if (kb >= maskStart) {
#pragma unroll
            for (int i = 0; i < 8; i++) {
                int gq = q0 + row8 + i;
#pragma unroll
                for (int j = 0; j < 4; j++) {
                    int gk = kb * 64 + col4 + j;
                    if (gk > gq) s[i][j] = -1e30f;
                }
            }
        }

#pragma unroll
        for (int i = 0; i < 8; i++) {
            float v = fmaxf(fmaxf(s[i][0], s[i][1]), fmaxf(s[i][2], s[i][3]));
#pragma unroll
            for (int o = 1; o < 16; o <<= 1)
                v = fmaxf(v, __shfl_xor_sync(0xffffffffu, v, o));
            float mnew  = fmaxf(m_i[i], v);
            float alpha = __expf(m_i[i] - mnew);
            m_i[i] = mnew;
            float ps = 0.f;
#pragma unroll
            for (int j = 0; j < 4; j++) {
                s[i][j] = __expf(s[i][j] - mnew);
                ps += s[i][j];
            }
#pragma unroll
            for (int o = 1; o < 16; o <<= 1)
                ps += __shfl_xor_sync(0xffffffffu, ps, o);
            l_i[i] = l_i[i] * alpha + ps;
            u64 ap = pack2(alpha);
            fmul2(O2[i][0], ap);
            fmul2(O2[i][1], ap);
        }

        __syncthreads();
#pragma unroll
        for (int i = 0; i < 8; i++)
            *(float4*)&Ps[row8 + i][col4] =
                make_float4(s[i][0], s[i][1], s[i][2], s[i][3]);
        __syncthreads();

        // ---- O += P @ V, packed: per 4-key step 32 packs + 64 FFMA2 ----
#pragma unroll 2
        for (int j = 0; j < 64; j += 4) {
            float4 pa[8];
#pragma unroll
            for (int i = 0; i < 8; i++) pa[i] = *(float4*)&Ps[row8 + i][j];
            float4 b0 = *(float4*)&Vs[j + 0][col4];
            float4 b1 = *(float4*)&Vs[j + 1][col4];
            float4 b2 = *(float4*)&Vs[j + 2][col4];
            float4 b3 = *(float4*)&Vs[j + 3][col4];
            u64 bp[4][2];
            bp[0][0] = ((const u64*)&b0)[0]; bp[0][1] = ((const u64*)&b0)[1];
            bp[1][0] = ((const u64*)&b1)[0]; bp[1][1] = ((const u64*)&b1)[1];
            bp[2][0] = ((const u64*)&b2)[0]; bp[2][1] = ((const u64*)&b2)[1];
            bp[3][0] = ((const u64*)&b3)[0]; bp[3][1] = ((const u64*)&b3)[1];
#pragma unroll
            for (int i = 0; i < 8; i++) {
                u64 ap;
                ap = pack2(pa[i].x);
                ffma2(O2[i][0], ap, bp[0][0]); ffma2(O2[i][1], ap, bp[0][1]);
                ap = pack2(pa[i].y);
                ffma2(O2[i][0], ap, bp[1][0]); ffma2(O2[i][1], ap, bp[1][1]);
                ap = pack2(pa[i].z);
                ffma2(O2[i][0], ap, bp[2][0]); ffma2(O2[i][1], ap, bp[2][1]);
                ap = pack2(pa[i].w);
                ffma2(O2[i][0], ap, bp[3][0]); ffma2(O2[i][1], ap, bp[3][1]);
            }
        }
    }

    const int b = bh >> 4, h = bh & 15;
#pragma unroll
    for (int i = 0; i < 8; i++) {
        float inv = 1.f / l_i[i];
        float o0, o1, o2, o3;
        unpack2(O2[i][0], o0, o1);
        unpack2(O2[i][1], o2, o3);
        int t = q0 + row8 + i;
        float* p = g_y + ((size_t)b * TT + t) * CC + h * DD + col4;
        *(float4*)p = make_float4(o0 * inv, o1 * inv, o2 * inv, o3 * inv);
    }
}

// ---------------------------------------------------------------------------
extern "C" void kernel_launch(void* const* d_in, const int* in_sizes, int n_in,
                              void* d_out, int out_size)
{
    (void)in_sizes; (void)n_in; (void)out_size;
    const float* x      = (const float*)d_in[0];
    const float* W_attn = (const float*)d_in[1];
    const float* b_attn = (const float*)d_in[2];
    const float* W_proj = (const float*)d_in[3];
    const float* b_proj = (const float*)d_in[4];
    float* out = (float*)d_out;

    cudaFuncSetAttribute(attn_kernel,
                         cudaFuncAttributeMaxDynamicSharedMemorySize,
                         ATTN_SMEM_BYTES);

    qkv_p2_kernel <<<dim3(3072 / 128, MROWS / 128), 256>>>(x, W_attn, b_attn);
    attn_kernel   <<<dim3(TT / 128, BB * HH), 256, ATTN_SMEM_BYTES>>>();
    proj_p2_kernel<<<dim3(CC / 128, MROWS / 128), 256>>>(W_proj, b_proj, out);
}

// round 14
// speedup vs baseline: 1.1027x; 1.0019x over previous
#include <cuda_runtime.h>
#include <cstdint>

// Problem constants
#define BB   4
#define TT   2048
#define CC   1024
#define HH   16
#define DD   64
#define MROWS (BB*TT)      // 8192

// Scratch (static device globals — accessed ONLY via symbol inside kernels;
// never passed as kernel arguments from host code).
__device__ float g_q[BB*HH*TT*DD];   // [B,H,T,d]
__device__ float g_k[BB*HH*TT*DD];
__device__ float g_v[BB*HH*TT*DD];
__device__ float g_y[BB*TT*CC];      // attention output, [B,T,C]

// ============================================================================
// Packed f32x2 + cp.async helpers
// ============================================================================
typedef unsigned long long u64;

__device__ __forceinline__ u64 pack2(float x) {
    u64 r;
    asm("mov.b64 %0, {%1, %1};" : "=l"(r) : "f"(x));
    return r;
}
__device__ __forceinline__ void ffma2(u64& d, u64 a, u64 b) {
    asm("fma.rn.f32x2 %0, %1, %2, %0;" : "+l"(d) : "l"(a), "l"(b));
}
__device__ __forceinline__ void fmul2(u64& d, u64 a) {
    asm("mul.rn.f32x2 %0, %0, %1;" : "+l"(d) : "l"(a));
}
__device__ __forceinline__ void unpack2(u64 v, float& lo, float& hi) {
    asm("mov.b64 {%0, %1}, %2;" : "=f"(lo), "=f"(hi) : "l"(v));
}
__device__ __forceinline__ uint32_t smem_u32_of(const void* p) {
    uint32_t a;
    asm("{ .reg .u64 t; cvta.to.shared.u64 t, %1; cvt.u32.u64 %0, t; }"
        : "=r"(a) : "l"(p));
    return a;
}
#define CPG16(dst_sm, src) \
    asm volatile("cp.async.cg.shared.global [%0], [%1], 16;" \
                 :: "r"(dst_sm), "l"(src))
#define CP_COMMIT() asm volatile("cp.async.commit_group;" ::: "memory")
#define CP_WAIT0()  asm volatile("cp.async.wait_group 0;" ::: "memory")

// ============================================================================
// Packed-FMA GEMM, double-buffered (UNCHANGED from Round-12/13 winner).
// ============================================================================
__global__ __launch_bounds__(256, 1)
void qkv_p2_kernel(const float* __restrict__ Ag, const float* __restrict__ Wg,
                   const float* __restrict__ bias)
{
    __shared__ float As[2][16][132];
    __shared__ float Bs[2][16][132];

    const int tid  = threadIdx.x;
    const int ty   = tid >> 4, tx = tid & 15;
    const int row8 = ty * 8,  col8 = tx * 8;
    const int m0   = blockIdx.y * 128;
    const int n0   = blockIdx.x * 128;

    const int ar = tid >> 1;
    const int aq = (tid & 1) * 8;
    const int bk = tid >> 4;
    const int bc = tid & 15;

    const float* aptr = Ag + (size_t)(m0 + ar) * 1024 + aq;

    u64 acc2[8][4];
#pragma unroll
    for (int i = 0; i < 8; i++)
#pragma unroll
        for (int j = 0; j < 4; j++) acc2[i][j] = 0ull;

    float4 av0, av1, bv0, bv1;

    const int c0 = bc, c1 = bc + 16;
    const int j0 = (((c0 & 15) << 1) | (c0 >> 4)) * 4;
    const int j1 = (((c1 & 15) << 1) | (c1 >> 4)) * 4;
    const float* bptr0 = Wg + (size_t)bk * 3072 + n0 + j0;
    const float* bptr1 = Wg + (size_t)bk * 3072 + n0 + j1;

#define LDG_CHUNK(S)                                                          \
    do {                                                                      \
        av0 = *(const float4*)(aptr + (S) * 16);                              \
        av1 = *(const float4*)(aptr + (S) * 16 + 4);                          \
        bv0 = *(const float4*)(bptr0 + (size_t)(S) * 16 * 3072);              \
        bv1 = *(const float4*)(bptr1 + (size_t)(S) * 16 * 3072);              \
    } while (0)

#define STS_CHUNK(BUF)                                                        \
    do {                                                                      \
        As[BUF][aq + 0][ar] = av0.x; As[BUF][aq + 1][ar] = av0.y;             \
        As[BUF][aq + 2][ar] = av0.z; As[BUF][aq + 3][ar] = av0.w;             \
        As[BUF][aq + 4][ar] = av1.x; As[BUF][aq + 5][ar] = av1.y;             \
        As[BUF][aq + 6][ar] = av1.z; As[BUF][aq + 7][ar] = av1.w;             \
        *(float4*)&Bs[BUF][bk][4 * c0] = bv0;                                 \
        *(float4*)&Bs[BUF][bk][4 * c1] = bv1;                                 \
    } while (0)

    LDG_CHUNK(0);
    STS_CHUNK(0);
    __syncthreads();

    for (int s = 0; s < 64; s++) {
        const int buf = s & 1;
        if (s < 63) LDG_CHUNK(s + 1);

#pragma unroll
        for (int kk = 0; kk < 16; kk++) {
            float a[8];
            *(float4*)&a[0] = *(float4*)&As[buf][kk][row8];
            *(float4*)&a[4] = *(float4*)&As[buf][kk][row8 + 4];
            float4 b0 = *(float4*)&Bs[buf][kk][4 * tx];
            float4 b1 = *(float4*)&Bs[buf][kk][64 + 4 * tx];
            u64 bp[4];
            bp[0] = ((const u64*)&b0)[0];
            bp[1] = ((const u64*)&b0)[1];
            bp[2] = ((const u64*)&b1)[0];
            bp[3] = ((const u64*)&b1)[1];
#pragma unroll
            for (int i = 0; i < 8; i++) {
                u64 ap = pack2(a[i]);
                ffma2(acc2[i][0], ap, bp[0]);
                ffma2(acc2[i][1], ap, bp[1]);
                ffma2(acc2[i][2], ap, bp[2]);
                ffma2(acc2[i][3], ap, bp[3]);
            }
        }

        if (s < 63) STS_CHUNK(buf ^ 1);
        __syncthreads();
    }
#undef LDG_CHUNK
#undef STS_CHUNK

    float bvv[8];
#pragma unroll
    for (int j = 0; j < 8; j++) bvv[j] = bias[n0 + col8 + j];

    int sel = (n0 + col8) >> 10;
    int cc0 = (n0 + col8) & 1023;
    int h   = cc0 >> 6;
    int dd  = cc0 & 63;
    float* dst = (sel == 0) ? g_q : ((sel == 1) ? g_k : g_v);
#pragma unroll
    for (int i = 0; i < 8; i++) {
        float acc[8];
#pragma unroll
        for (int jp = 0; jp < 4; jp++)
            unpack2(acc2[i][jp], acc[2 * jp], acc[2 * jp + 1]);
        int m = m0 + row8 + i;
        int b_ = m >> 11, t = m & 2047;
        float* p = dst + ((size_t)((b_ * HH + h) * TT + t)) * DD + dd;
        *(float4*)p = make_float4(acc[0] + bvv[0], acc[1] + bvv[1],
                                  acc[2] + bvv[2], acc[3] + bvv[3]);
        *(float4*)(p + 4) = make_float4(acc[4] + bvv[4], acc[5] + bvv[5],
                                        acc[6] + bvv[6], acc[7] + bvv[7]);
    }
}

__global__ __launch_bounds__(256, 1)
void proj_p2_kernel(const float* __restrict__ Wg, const float* __restrict__ bias,
                    float* __restrict__ out)
{
    __shared__ float As[2][16][132];
    __shared__ float Bs[2][16][132];

    const int tid  = threadIdx.x;
    const int ty   = tid >> 4, tx = tid & 15;
    const int row8 = ty * 8,  col8 = tx * 8;
    const int m0   = blockIdx.y * 128;
    const int n0   = blockIdx.x * 128;

    const int ar = tid >> 1;
    const int aq = (tid & 1) * 8;
    const int bk = tid >> 4;
    const int bc = tid & 15;

    const float* aptr = g_y + (size_t)(m0 + ar) * 1024 + aq;   // symbol access

    u64 acc2[8][4];
#pragma unroll
    for (int i = 0; i < 8; i++)
#pragma unroll
        for (int j = 0; j < 4; j++) acc2[i][j] = 0ull;

    float4 av0, av1, bv0, bv1;

    const int c0 = bc, c1 = bc + 16;
    const int j0 = (((c0 & 15) << 1) | (c0 >> 4)) * 4;
    const int j1 = (((c1 & 15) << 1) | (c1 >> 4)) * 4;
    const float* bptr0 = Wg + (size_t)bk * CC + n0 + j0;
    const float* bptr1 = Wg + (size_t)bk * CC + n0 + j1;

#define LDG_CHUNK(S)                                                          \
    do {                                                                      \
        av0 = *(const float4*)(aptr + (S) * 16);                              \
        av1 = *(const float4*)(aptr + (S) * 16 + 4);                          \
        bv0 = *(const float4*)(bptr0 + (size_t)(S) * 16 * CC);                \
        bv1 = *(const float4*)(bptr1 + (size_t)(S) * 16 * CC);                \
    } while (0)

#define STS_CHUNK(BUF)                                                        \
    do {                                                                      \
        As[BUF][aq + 0][ar] = av0.x; As[BUF][aq + 1][ar] = av0.y;             \
        As[BUF][aq + 2][ar] = av0.z; As[BUF][aq + 3][ar] = av0.w;             \
        As[BUF][aq + 4][ar] = av1.x; As[BUF][aq + 5][ar] = av1.y;             \
        As[BUF][aq + 6][ar] = av1.z; As[BUF][aq + 7][ar] = av1.w;             \
        *(float4*)&Bs[BUF][bk][4 * c0] = bv0;                                 \
        *(float4*)&Bs[BUF][bk][4 * c1] = bv1;                                 \
    } while (0)

    LDG_CHUNK(0);
    STS_CHUNK(0);
    __syncthreads();

    for (int s = 0; s < 64; s++) {
        const int buf = s & 1;
        if (s < 63) LDG_CHUNK(s + 1);

#pragma unroll
        for (int kk = 0; kk < 16; kk++) {
            float a[8];
            *(float4*)&a[0] = *(float4*)&As[buf][kk][row8];
            *(float4*)&a[4] = *(float4*)&As[buf][kk][row8 + 4];
            float4 b0 = *(float4*)&Bs[buf][kk][4 * tx];
            float4 b1 = *(float4*)&Bs[buf][kk][64 + 4 * tx];
            u64 bp[4];
            bp[0] = ((const u64*)&b0)[0];
            bp[1] = ((const u64*)&b0)[1];
            bp[2] = ((const u64*)&b1)[0];
            bp[3] = ((const u64*)&b1)[1];
#pragma unroll
            for (int i = 0; i < 8; i++) {
                u64 ap = pack2(a[i]);
                ffma2(acc2[i][0], ap, bp[0]);
                ffma2(acc2[i][1], ap, bp[1]);
                ffma2(acc2[i][2], ap, bp[2]);
                ffma2(acc2[i][3], ap, bp[3]);
            }
        }

        if (s < 63) STS_CHUNK(buf ^ 1);
        __syncthreads();
    }
#undef LDG_CHUNK
#undef STS_CHUNK

    float bvv[8];
#pragma unroll
    for (int j = 0; j < 8; j++) bvv[j] = bias[n0 + col8 + j];
#pragma unroll
    for (int i = 0; i < 8; i++) {
        float acc[8];
#pragma unroll
        for (int jp = 0; jp < 4; jp++)
            unpack2(acc2[i][jp], acc[2 * jp], acc[2 * jp + 1]);
        int m = m0 + row8 + i;
        float* p = out + (size_t)m * CC + n0 + col8;
        *(float4*)p = make_float4(acc[0] + bvv[0], acc[1] + bvv[1],
                                  acc[2] + bvv[2], acc[3] + bvv[3]);
        *(float4*)(p + 4) = make_float4(acc[4] + bvv[4], acc[5] + bvv[5],
                                        acc[6] + bvv[6], acc[7] + bvv[7]);
    }
}

// ---------------------------------------------------------------------------
// Kernel 2: Flash attention (causal), fp32, online softmax, packed f32x2.
// Round-14 changes (arithmetic order per element unchanged):
//  - S-loop row-paired: Q pairs come free as u64 reads of contiguous Qt rows;
//    only 4 K packs per dd (was 8 Q packs).
//  - Ps in its OWN buffer (no Kt alias): 3 barriers per block (was 4).
//  - V tile via cp.async issued at block top, waited just before PV:
//    V global latency hidden behind S + softmax; zero staging registers.
// Smem: Qt[64][132] + Kt[64][68] + Vs[64][68] + Ps[128][68] = 103,424 B
// (2 CTA/SM: 206,848 <= 227 KB).
// ---------------------------------------------------------------------------
#define ATTN_SMEM_FLOATS (64*132 + 64*68 + 64*68 + 128*68)
#define ATTN_SMEM_BYTES  (ATTN_SMEM_FLOATS * 4)

__global__ __launch_bounds__(256, 2)
void attn_kernel()
{
    extern __shared__ float smem[];
    float (*Qt)[132] = (float(*)[132])smem;                        // [d][query]
    float (*Kt)[68]  = (float(*)[68])(smem + 64 * 132);            // [d][key]
    float (*Vs)[68]  = (float(*)[68])(smem + 64 * 132 + 64 * 68);  // [key][d]
    float (*Ps)[68]  = (float(*)[68])(smem + 64 * 132 + 2 * 64 * 68); // [q][key]

    const int tid  = threadIdx.x;
    const int ty   = tid >> 4, tx = tid & 15;
    const int row8 = ty * 8;
    const int col4 = tx * 4;

    const int q0 = blockIdx.x * 128;
    const int bh = blockIdx.y;        // b*16 + h
    const float* qbase = g_q + ((size_t)bh * TT + q0) * DD;
    const uint32_t vs_base = smem_u32_of(&Vs[0][0]);

    const float scale = 0.125f;
#pragma unroll
    for (int it = 0; it < 8; it++) {
        int idx = tid + 256 * it;
        int r   = idx >> 4;
        int dq  = (idx & 15) * 4;
        float4 v = *(const float4*)(qbase + (size_t)r * DD + dq);
        Qt[dq + 0][r] = v.x * scale; Qt[dq + 1][r] = v.y * scale;
        Qt[dq + 2][r] = v.z * scale; Qt[dq + 3][r] = v.w * scale;
    }

    float m_i[8], l_i[8];
    u64 O2[8][2];                      // O pairs: (c0,c1),(c2,c3)
#pragma unroll
    for (int i = 0; i < 8; i++) {
        m_i[i] = -1e30f; l_i[i] = 0.f;
        O2[i][0] = 0ull; O2[i][1] = 0ull;
    }

    const int maskStart = q0 >> 6;
    const int nblk      = maskStart + 2;

    for (int kb = 0; kb < nblk; kb++) {
        __syncthreads();   // sync1: prev S read Kt, prev PV read Ps/Vs done
                           //        (also orders Qt fill for kb==0)

        // V: cp.async issue (consumed at PV; latency hidden by S + softmax)
        {
            const float* vb = g_v + ((size_t)bh * TT + kb * 64) * DD;
#pragma unroll
            for (int it = 0; it < 4; it++) {
                int idx = tid + 256 * it;
                int r   = idx >> 4;
                int dq  = (idx & 15) * 4;
                CPG16(vs_base + (r * 68 + dq) * 4, vb + (size_t)r * DD + dq);
            }
            CP_COMMIT();
        }

        // K: LDG + STS transpose
        {
            const float* kbase = g_k + ((size_t)bh * TT + kb * 64) * DD;
#pragma unroll
            for (int it = 0; it < 4; it++) {
                int idx = tid + 256 * it;
                int r   = idx >> 4;
                int dq  = (idx & 15) * 4;
                float4 kv = *(const float4*)(kbase + (size_t)r * DD + dq);
                Kt[dq + 0][r] = kv.x; Kt[dq + 1][r] = kv.y;
                Kt[dq + 2][r] = kv.z; Kt[dq + 3][r] = kv.w;
            }
        }
        __syncthreads();   // sync2: Kt ready

        // ---- S = Q K^T, row-paired: per dd 4 packs (K) + 16 FFMA2;
        //      Q pairs free from contiguous u64 reads of Qt[dd][row8..] ----
        u64 s2[4][4];      // [row-pair p][col j] = (s[2p][j], s[2p+1][j])
#pragma unroll
        for (int p = 0; p < 4; p++)
#pragma unroll
            for (int j = 0; j < 4; j++) s2[p][j] = 0ull;

#pragma unroll 4
        for (int dd = 0; dd < 64; dd++) {
            float4 a0 = *(float4*)&Qt[dd][row8];
            float4 a1 = *(float4*)&Qt[dd][row8 + 4];
            u64 qp[4];
            qp[0] = ((const u64*)&a0)[0];      // (q r, q r+1)
            qp[1] = ((const u64*)&a0)[1];      // (q r+2, q r+3)
            qp[2] = ((const u64*)&a1)[0];
            qp[3] = ((const u64*)&a1)[1];
            float4 bq = *(float4*)&Kt[dd][col4];
            u64 k0 = pack2(bq.x), k1 = pack2(bq.y),
                k2 = pack2(bq.z), k3 = pack2(bq.w);
#pragma unroll
            for (int p = 0; p < 4; p++) {
                ffma2(s2[p][0], qp[p], k0);
                ffma2(s2[p][1], qp[p], k1);
                ffma2(s2[p][2], qp[p], k2);
                ffma2(s2[p][3], qp[p], k3);
            }
        }

        // Unpack scores (s[i][j], i = query row offset within row8 block)
        float s[8][4];
#pragma unroll
        for (int p = 0; p < 4; p++)
#pragma unroll
            for (int j = 0; j < 4; j++)
                unpack2(s2[p][j], s[2 * p][j], s[2 * p + 1][j]);

        if (kb >= maskStart) {
#pragma unroll
            for (int i = 0; i < 8; i++) {
                int gq = q0 + row8 + i;
#pragma unroll
                for (int j = 0; j < 4; j++) {
                    int gk = kb * 64 + col4 + j;
                    if (gk > gq) s[i][j] = -1e30f;
                }
            }
        }

#pragma unroll
        for (int i = 0; i < 8; i++) {
            float v = fmaxf(fmaxf(s[i][0], s[i][1]), fmaxf(s[i][2], s[i][3]));
#pragma unroll
            for (int o = 1; o < 16; o <<= 1)
                v = fmaxf(v, __shfl_xor_sync(0xffffffffu, v, o));
            float mnew  = fmaxf(m_i[i], v);
            float alpha = __expf(m_i[i] - mnew);
            m_i[i] = mnew;
            float ps = 0.f;
#pragma unroll
            for (int j = 0; j < 4; j++) {
                s[i][j] = __expf(s[i][j] - mnew);
                ps += s[i][j];
            }
#pragma unroll
            for (int o = 1; o < 16; o <<= 1)
                ps += __shfl_xor_sync(0xffffffffu, ps, o);
            l_i[i] = l_i[i] * alpha + ps;
            u64 ap = pack2(alpha);
            fmul2(O2[i][0], ap);
            fmul2(O2[i][1], ap);
        }

        // P -> smem (own buffer; no Kt-alias barrier needed)
#pragma unroll
        for (int i = 0; i < 8; i++)
            *(float4*)&Ps[row8 + i][col4] =
                make_float4(s[i][0], s[i][1], s[i][2], s[i][3]);

        CP_WAIT0();        // this thread's V chunks landed
        __syncthreads();   // sync3: Ps + Vs visible to all

        // ---- O += P @ V (column-paired; V pairs free) ----
#pragma unroll 2
        for (int j = 0; j < 64; j += 4) {
            float4 pa[8];
#pragma unroll
            for (int i = 0; i < 8; i++) pa[i] = *(float4*)&Ps[row8 + i][j];
            float4 b0 = *(float4*)&Vs[j + 0][col4];
            float4 b1 = *(float4*)&Vs[j + 1][col4];
            float4 b2 = *(float4*)&Vs[j + 2][col4];
            float4 b3 = *(float4*)&Vs[j + 3][col4];
            u64 bp[4][2];
            bp[0][0] = ((const u64*)&b0)[0]; bp[0][1] = ((const u64*)&b0)[1];
            bp[1][0] = ((const u64*)&b1)[0]; bp[1][1] = ((const u64*)&b1)[1];
            bp[2][0] = ((const u64*)&b2)[0]; bp[2][1] = ((const u64*)&b2)[1];
            bp[3][0] = ((const u64*)&b3)[0]; bp[3][1] = ((const u64*)&b3)[1];
#pragma unroll
            for (int i = 0; i < 8; i++) {
                u64 ap;
                ap = pack2(pa[i].x);
                ffma2(O2[i][0], ap, bp[0][0]); ffma2(O2[i][1], ap, bp[0][1]);
                ap = pack2(pa[i].y);
                ffma2(O2[i][0], ap, bp[1][0]); ffma2(O2[i][1], ap, bp[1][1]);
                ap = pack2(pa[i].z);
                ffma2(O2[i][0], ap, bp[2][0]); ffma2(O2[i][1], ap, bp[2][1]);
                ap = pack2(pa[i].w);
                ffma2(O2[i][0], ap, bp[3][0]); ffma2(O2[i][1], ap, bp[3][1]);
            }
        }
    }

    const int b = bh >> 4, h = bh & 15;
#pragma unroll
    for (int i = 0; i < 8; i++) {
        float inv = 1.f / l_i[i];
        float o0, o1, o2, o3;
        unpack2(O2[i][0], o0, o1);
        unpack2(O2[i][1], o2, o3);
        int t = q0 + row8 + i;
        float* p = g_y + ((size_t)b * TT + t) * CC + h * DD + col4;
        *(float4*)p = make_float4(o0 * inv, o1 * inv, o2 * inv, o3 * inv);
    }
}

// ---------------------------------------------------------------------------
extern "C" void kernel_launch(void* const* d_in, const int* in_sizes, int n_in,
                              void* d_out, int out_size)
{
    (void)in_sizes; (void)n_in; (void)out_size;
    const float* x      = (const float*)d_in[0];
    const float* W_attn = (const float*)d_in[1];
    const float* b_attn = (const float*)d_in[2];
    const float* W_proj = (const float*)d_in[3];
    const float* b_proj = (const float*)d_in[4];
    float* out = (float*)d_out;

    cudaFuncSetAttribute(attn_kernel,
                         cudaFuncAttributeMaxDynamicSharedMemorySize,
                         ATTN_SMEM_BYTES);

    qkv_p2_kernel <<<dim3(3072 / 128, MROWS / 128), 256>>>(x, W_attn, b_attn);
    attn_kernel   <<<dim3(TT / 128, BB * HH), 256, ATTN_SMEM_BYTES>>>();
    proj_p2_kernel<<<dim3(CC / 128, MROWS / 128), 256>>>(W_proj, b_proj, out);
}

// round 15
// speedup vs baseline: 1.2166x; 1.1033x over previous
#include <cuda_runtime.h>
#include <cstdint>

// Problem constants
#define BB   4
#define TT   2048
#define CC   1024
#define HH   16
#define DD   64
#define MROWS (BB*TT)      // 8192

// Scratch (static device globals — accessed ONLY via symbol inside kernels;
// never passed as kernel arguments from host code).
__device__ float g_q[BB*HH*TT*DD];   // [B,H,T,d]
__device__ float g_k[BB*HH*TT*DD];
__device__ float g_v[BB*HH*TT*DD];
__device__ float g_y[BB*TT*CC];      // attention output, [B,T,C]

// ============================================================================
// Packed f32x2 + cp.async helpers
// ============================================================================
typedef unsigned long long u64;

__device__ __forceinline__ u64 pack2(float x) {
    u64 r;
    asm("mov.b64 %0, {%1, %1};" : "=l"(r) : "f"(x));
    return r;
}
__device__ __forceinline__ void ffma2(u64& d, u64 a, u64 b) {
    asm("fma.rn.f32x2 %0, %1, %2, %0;" : "+l"(d) : "l"(a), "l"(b));
}
__device__ __forceinline__ void fmul2(u64& d, u64 a) {
    asm("mul.rn.f32x2 %0, %0, %1;" : "+l"(d) : "l"(a));
}
__device__ __forceinline__ void unpack2(u64 v, float& lo, float& hi) {
    asm("mov.b64 {%0, %1}, %2;" : "=f"(lo), "=f"(hi) : "l"(v));
}
__device__ __forceinline__ uint32_t smem_u32_of(const void* p) {
    uint32_t a;
    asm("{ .reg .u64 t; cvta.to.shared.u64 t, %1; cvt.u32.u64 %0, t; }"
        : "=r"(a) : "l"(p));
    return a;
}
#define CPG16(dst_sm, src) \
    asm volatile("cp.async.cg.shared.global [%0], [%1], 16;" \
                 :: "r"(dst_sm), "l"(src))
#define CP_COMMIT() asm volatile("cp.async.commit_group;" ::: "memory")
#define CP_WAIT0()  asm volatile("cp.async.wait_group 0;" ::: "memory")

// ============================================================================
// Packed-FMA GEMM, double-buffered (UNCHANGED from Round-12/13/14 winner).
// ============================================================================
__global__ __launch_bounds__(256, 1)
void qkv_p2_kernel(const float* __restrict__ Ag, const float* __restrict__ Wg,
                   const float* __restrict__ bias)
{
    __shared__ float As[2][16][132];
    __shared__ float Bs[2][16][132];

    const int tid  = threadIdx.x;
    const int ty   = tid >> 4, tx = tid & 15;
    const int row8 = ty * 8,  col8 = tx * 8;
    const int m0   = blockIdx.y * 128;
    const int n0   = blockIdx.x * 128;

    const int ar = tid >> 1;
    const int aq = (tid & 1) * 8;
    const int bk = tid >> 4;
    const int bc = tid & 15;

    const float* aptr = Ag + (size_t)(m0 + ar) * 1024 + aq;

    u64 acc2[8][4];
#pragma unroll
    for (int i = 0; i < 8; i++)
#pragma unroll
        for (int j = 0; j < 4; j++) acc2[i][j] = 0ull;

    float4 av0, av1, bv0, bv1;

    const int c0 = bc, c1 = bc + 16;
    const int j0 = (((c0 & 15) << 1) | (c0 >> 4)) * 4;
    const int j1 = (((c1 & 15) << 1) | (c1 >> 4)) * 4;
    const float* bptr0 = Wg + (size_t)bk * 3072 + n0 + j0;
    const float* bptr1 = Wg + (size_t)bk * 3072 + n0 + j1;

#define LDG_CHUNK(S)                                                          \
    do {                                                                      \
        av0 = *(const float4*)(aptr + (S) * 16);                              \
        av1 = *(const float4*)(aptr + (S) * 16 + 4);                          \
        bv0 = *(const float4*)(bptr0 + (size_t)(S) * 16 * 3072);              \
        bv1 = *(const float4*)(bptr1 + (size_t)(S) * 16 * 3072);              \
    } while (0)

#define STS_CHUNK(BUF)                                                        \
    do {                                                                      \
        As[BUF][aq + 0][ar] = av0.x; As[BUF][aq + 1][ar] = av0.y;             \
        As[BUF][aq + 2][ar] = av0.z; As[BUF][aq + 3][ar] = av0.w;             \
        As[BUF][aq + 4][ar] = av1.x; As[BUF][aq + 5][ar] = av1.y;             \
        As[BUF][aq + 6][ar] = av1.z; As[BUF][aq + 7][ar] = av1.w;             \
        *(float4*)&Bs[BUF][bk][4 * c0] = bv0;                                 \
        *(float4*)&Bs[BUF][bk][4 * c1] = bv1;                                 \
    } while (0)

    LDG_CHUNK(0);
    STS_CHUNK(0);
    __syncthreads();

    for (int s = 0; s < 64; s++) {
        const int buf = s & 1;
        if (s < 63) LDG_CHUNK(s + 1);

#pragma unroll
        for (int kk = 0; kk < 16; kk++) {
            float a[8];
            *(float4*)&a[0] = *(float4*)&As[buf][kk][row8];
            *(float4*)&a[4] = *(float4*)&As[buf][kk][row8 + 4];
            float4 b0 = *(float4*)&Bs[buf][kk][4 * tx];
            float4 b1 = *(float4*)&Bs[buf][kk][64 + 4 * tx];
            u64 bp[4];
            bp[0] = ((const u64*)&b0)[0];
            bp[1] = ((const u64*)&b0)[1];
            bp[2] = ((const u64*)&b1)[0];
            bp[3] = ((const u64*)&b1)[1];
#pragma unroll
            for (int i = 0; i < 8; i++) {
                u64 ap = pack2(a[i]);
                ffma2(acc2[i][0], ap, bp[0]);
                ffma2(acc2[i][1], ap, bp[1]);
                ffma2(acc2[i][2], ap, bp[2]);
                ffma2(acc2[i][3], ap, bp[3]);
            }
        }

        if (s < 63) STS_CHUNK(buf ^ 1);
        __syncthreads();
    }
#undef LDG_CHUNK
#undef STS_CHUNK

    float bvv[8];
#pragma unroll
    for (int j = 0; j < 8; j++) bvv[j] = bias[n0 + col8 + j];

    int sel = (n0 + col8) >> 10;
    int cc0 = (n0 + col8) & 1023;
    int h   = cc0 >> 6;
    int dd  = cc0 & 63;
    float* dst = (sel == 0) ? g_q : ((sel == 1) ? g_k : g_v);
#pragma unroll
    for (int i = 0; i < 8; i++) {
        float acc[8];
#pragma unroll
        for (int jp = 0; jp < 4; jp++)
            unpack2(acc2[i][jp], acc[2 * jp], acc[2 * jp + 1]);
        int m = m0 + row8 + i;
        int b_ = m >> 11, t = m & 2047;
        float* p = dst + ((size_t)((b_ * HH + h) * TT + t)) * DD + dd;
        *(float4*)p = make_float4(acc[0] + bvv[0], acc[1] + bvv[1],
                                  acc[2] + bvv[2], acc[3] + bvv[3]);
        *(float4*)(p + 4) = make_float4(acc[4] + bvv[4], acc[5] + bvv[5],
                                        acc[6] + bvv[6], acc[7] + bvv[7]);
    }
}

__global__ __launch_bounds__(256, 1)
void proj_p2_kernel(const float* __restrict__ Wg, const float* __restrict__ bias,
                    float* __restrict__ out)
{
    __shared__ float As[2][16][132];
    __shared__ float Bs[2][16][132];

    const int tid  = threadIdx.x;
    const int ty   = tid >> 4, tx = tid & 15;
    const int row8 = ty * 8,  col8 = tx * 8;
    const int m0   = blockIdx.y * 128;
    const int n0   = blockIdx.x * 128;

    const int ar = tid >> 1;
    const int aq = (tid & 1) * 8;
    const int bk = tid >> 4;
    const int bc = tid & 15;

    const float* aptr = g_y + (size_t)(m0 + ar) * 1024 + aq;   // symbol access

    u64 acc2[8][4];
#pragma unroll
    for (int i = 0; i < 8; i++)
#pragma unroll
        for (int j = 0; j < 4; j++) acc2[i][j] = 0ull;

    float4 av0, av1, bv0, bv1;

    const int c0 = bc, c1 = bc + 16;
    const int j0 = (((c0 & 15) << 1) | (c0 >> 4)) * 4;
    const int j1 = (((c1 & 15) << 1) | (c1 >> 4)) * 4;
    const float* bptr0 = Wg + (size_t)bk * CC + n0 + j0;
    const float* bptr1 = Wg + (size_t)bk * CC + n0 + j1;

#define LDG_CHUNK(S)                                                          \
    do {                                                                      \
        av0 = *(const float4*)(aptr + (S) * 16);                              \
        av1 = *(const float4*)(aptr + (S) * 16 + 4);                          \
        bv0 = *(const float4*)(bptr0 + (size_t)(S) * 16 * CC);                \
        bv1 = *(const float4*)(bptr1 + (size_t)(S) * 16 * CC);                \
    } while (0)

#define STS_CHUNK(BUF)                                                        \
    do {                                                                      \
        As[BUF][aq + 0][ar] = av0.x; As[BUF][aq + 1][ar] = av0.y;             \
        As[BUF][aq + 2][ar] = av0.z; As[BUF][aq + 3][ar] = av0.w;             \
        As[BUF][aq + 4][ar] = av1.x; As[BUF][aq + 5][ar] = av1.y;             \
        As[BUF][aq + 6][ar] = av1.z; As[BUF][aq + 7][ar] = av1.w;             \
        *(float4*)&Bs[BUF][bk][4 * c0] = bv0;                                 \
        *(float4*)&Bs[BUF][bk][4 * c1] = bv1;                                 \
    } while (0)

    LDG_CHUNK(0);
    STS_CHUNK(0);
    __syncthreads();

    for (int s = 0; s < 64; s++) {
        const int buf = s & 1;
        if (s < 63) LDG_CHUNK(s + 1);

#pragma unroll
        for (int kk = 0; kk < 16; kk++) {
            float a[8];
            *(float4*)&a[0] = *(float4*)&As[buf][kk][row8];
            *(float4*)&a[4] = *(float4*)&As[buf][kk][row8 + 4];
            float4 b0 = *(float4*)&Bs[buf][kk][4 * tx];
            float4 b1 = *(float4*)&Bs[buf][kk][64 + 4 * tx];
            u64 bp[4];
            bp[0] = ((const u64*)&b0)[0];
            bp[1] = ((const u64*)&b0)[1];
            bp[2] = ((const u64*)&b1)[0];
            bp[3] = ((const u64*)&b1)[1];
#pragma unroll
            for (int i = 0; i < 8; i++) {
                u64 ap = pack2(a[i]);
                ffma2(acc2[i][0], ap, bp[0]);
                ffma2(acc2[i][1], ap, bp[1]);
                ffma2(acc2[i][2], ap, bp[2]);
                ffma2(acc2[i][3], ap, bp[3]);
            }
        }

        if (s < 63) STS_CHUNK(buf ^ 1);
        __syncthreads();
    }
#undef LDG_CHUNK
#undef STS_CHUNK

    float bvv[8];
#pragma unroll
    for (int j = 0; j < 8; j++) bvv[j] = bias[n0 + col8 + j];
#pragma unroll
    for (int i = 0; i < 8; i++) {
        float acc[8];
#pragma unroll
        for (int jp = 0; jp < 4; jp++)
            unpack2(acc2[i][jp], acc[2 * jp], acc[2 * jp + 1]);
        int m = m0 + row8 + i;
        float* p = out + (size_t)m * CC + n0 + col8;
        *(float4*)p = make_float4(acc[0] + bvv[0], acc[1] + bvv[1],
                                  acc[2] + bvv[2], acc[3] + bvv[3]);
        *(float4*)(p + 4) = make_float4(acc[4] + bvv[4], acc[5] + bvv[5],
                                        acc[6] + bvv[6], acc[7] + bvv[7]);
    }
}

// ---------------------------------------------------------------------------
// Kernel 2: Flash attention (causal), fp32, online softmax, packed f32x2.
// Round-15 change: HEAVY-FIRST GLOBAL SCHEDULING.
//   grid = (bh=64, qb=16); launch order is x-major, so making y the
//   (reversed) q-block axis puts ALL 64 heaviest CTAs (32 key-blocks each)
//   in the first scheduling wave; the tail wave holds only 2-unit CTAs.
//   Arithmetic is byte-identical to Round 14.
// ---------------------------------------------------------------------------
#define ATTN_SMEM_FLOATS (64*132 + 64*68 + 64*68 + 128*68)
#define ATTN_SMEM_BYTES  (ATTN_SMEM_FLOATS * 4)

__global__ __launch_bounds__(256, 2)
void attn_kernel()
{
    extern __shared__ float smem[];
    float (*Qt)[132] = (float(*)[132])smem;                        // [d][query]
    float (*Kt)[68]  = (float(*)[68])(smem + 64 * 132);            // [d][key]
    float (*Vs)[68]  = (float(*)[68])(smem + 64 * 132 + 64 * 68);  // [key][d]
    float (*Ps)[68]  = (float(*)[68])(smem + 64 * 132 + 2 * 64 * 68); // [q][key]

    const int tid  = threadIdx.x;
    const int ty   = tid >> 4, tx = tid & 15;
    const int row8 = ty * 8;
    const int col4 = tx * 4;

    // Heavy-first: y is the q-block axis, reversed (heaviest y=0 -> qb=15).
    const int q0 = (gridDim.y - 1 - blockIdx.y) * 128;
    const int bh = blockIdx.x;        // b*16 + h
    const float* qbase = g_q + ((size_t)bh * TT + q0) * DD;
    const uint32_t vs_base = smem_u32_of(&Vs[0][0]);

    const float scale = 0.125f;
#pragma unroll
    for (int it = 0; it < 8; it++) {
        int idx = tid + 256 * it;
        int r   = idx >> 4;
        int dq  = (idx & 15) * 4;
        float4 v = *(const float4*)(qbase + (size_t)r * DD + dq);
        Qt[dq + 0][r] = v.x * scale; Qt[dq + 1][r] = v.y * scale;
        Qt[dq + 2][r] = v.z * scale; Qt[dq + 3][r] = v.w * scale;
    }

    float m_i[8], l_i[8];
    u64 O2[8][2];                      // O pairs: (c0,c1),(c2,c3)
#pragma unroll
    for (int i = 0; i < 8; i++) {
        m_i[i] = -1e30f; l_i[i] = 0.f;
        O2[i][0] = 0ull; O2[i][1] = 0ull;
    }

    const int maskStart = q0 >> 6;
    const int nblk      = maskStart + 2;

    for (int kb = 0; kb < nblk; kb++) {
        __syncthreads();   // sync1: prev S read Kt, prev PV read Ps/Vs done

        // V: cp.async issue (consumed at PV; latency hidden by S + softmax)
        {
            const float* vb = g_v + ((size_t)bh * TT + kb * 64) * DD;
#pragma unroll
            for (int it = 0; it < 4; it++) {
                int idx = tid + 256 * it;
                int r   = idx >> 4;
                int dq  = (idx & 15) * 4;
                CPG16(vs_base + (r * 68 + dq) * 4, vb + (size_t)r * DD + dq);
            }
            CP_COMMIT();
        }

        // K: LDG + STS transpose
        {
            const float* kbase = g_k + ((size_t)bh * TT + kb * 64) * DD;
#pragma unroll
            for (int it = 0; it < 4; it++) {
                int idx = tid + 256 * it;
                int r   = idx >> 4;
                int dq  = (idx & 15) * 4;
                float4 kv = *(const float4*)(kbase + (size_t)r * DD + dq);
                Kt[dq + 0][r] = kv.x; Kt[dq + 1][r] = kv.y;
                Kt[dq + 2][r] = kv.z; Kt[dq + 3][r] = kv.w;
            }
        }
        __syncthreads();   // sync2: Kt ready

        // ---- S = Q K^T, row-paired (Q pairs free from contiguous Qt) ----
        u64 s2[4][4];      // [row-pair p][col j]
#pragma unroll
        for (int p = 0; p < 4; p++)
#pragma unroll
            for (int j = 0; j < 4; j++) s2[p][j] = 0ull;

#pragma unroll 4
        for (int dd = 0; dd < 64; dd++) {
            float4 a0 = *(float4*)&Qt[dd][row8];
            float4 a1 = *(float4*)&Qt[dd][row8 + 4];
            u64 qp[4];
            qp[0] = ((const u64*)&a0)[0];
            qp[1] = ((const u64*)&a0)[1];
            qp[2] = ((const u64*)&a1)[0];
            qp[3] = ((const u64*)&a1)[1];
            float4 bq = *(float4*)&Kt[dd][col4];
            u64 k0 = pack2(bq.x), k1 = pack2(bq.y),
                k2 = pack2(bq.z), k3 = pack2(bq.w);
#pragma unroll
            for (int p = 0; p < 4; p++) {
                ffma2(s2[p][0], qp[p], k0);
                ffma2(s2[p][1], qp[p], k1);
                ffma2(s2[p][2], qp[p], k2);
                ffma2(s2[p][3], qp[p], k3);
            }
        }

        float s[8][4];
#pragma unroll
        for (int p = 0; p < 4; p++)
#pragma unroll
            for (int j = 0; j < 4; j++)
                unpack2(s2[p][j], s[2 * p][j], s[2 * p + 1][j]);

        if (kb >= maskStart) {
#pragma unroll
            for (int i = 0; i < 8; i++) {
                int gq = q0 + row8 + i;
#pragma unroll
                for (int j = 0; j < 4; j++) {
                    int gk = kb * 64 + col4 + j;
                    if (gk > gq) s[i][j] = -1e30f;
                }
            }
        }

#pragma unroll
        for (int i = 0; i < 8; i++) {
            float v = fmaxf(fmaxf(s[i][0], s[i][1]), fmaxf(s[i][2], s[i][3]));
#pragma unroll
            for (int o = 1; o < 16; o <<= 1)
                v = fmaxf(v, __shfl_xor_sync(0xffffffffu, v, o));
            float mnew  = fmaxf(m_i[i], v);
            float alpha = __expf(m_i[i] - mnew);
            m_i[i] = mnew;
            float ps = 0.f;
#pragma unroll
            for (int j = 0; j < 4; j++) {
                s[i][j] = __expf(s[i][j] - mnew);
                ps += s[i][j];
            }
#pragma unroll
            for (int o = 1; o < 16; o <<= 1)
                ps += __shfl_xor_sync(0xffffffffu, ps, o);
            l_i[i] = l_i[i] * alpha + ps;
            u64 ap = pack2(alpha);
            fmul2(O2[i][0], ap);
            fmul2(O2[i][1], ap);
        }

        // P -> smem (own buffer)
#pragma unroll
        for (int i = 0; i < 8; i++)
            *(float4*)&Ps[row8 + i][col4] =
                make_float4(s[i][0], s[i][1], s[i][2], s[i][3]);

        CP_WAIT0();        // this thread's V chunks landed
        __syncthreads();   // sync3: Ps + Vs visible to all

        // ---- O += P @ V (column-paired; V pairs free) ----
#pragma unroll 2
        for (int j = 0; j < 64; j += 4) {
            float4 pa[8];
#pragma unroll
            for (int i = 0; i < 8; i++) pa[i] = *(float4*)&Ps[row8 + i][j];
            float4 b0 = *(float4*)&Vs[j + 0][col4];
            float4 b1 = *(float4*)&Vs[j + 1][col4];
            float4 b2 = *(float4*)&Vs[j + 2][col4];
            float4 b3 = *(float4*)&Vs[j + 3][col4];
            u64 bp[4][2];
            bp[0][0] = ((const u64*)&b0)[0]; bp[0][1] = ((const u64*)&b0)[1];
            bp[1][0] = ((const u64*)&b1)[0]; bp[1][1] = ((const u64*)&b1)[1];
            bp[2][0] = ((const u64*)&b2)[0]; bp[2][1] = ((const u64*)&b2)[1];
            bp[3][0] = ((const u64*)&b3)[0]; bp[3][1] = ((const u64*)&b3)[1];
#pragma unroll
            for (int i = 0; i < 8; i++) {
                u64 ap;
                ap = pack2(pa[i].x);
                ffma2(O2[i][0], ap, bp[0][0]); ffma2(O2[i][1], ap, bp[0][1]);
                ap = pack2(pa[i].y);
                ffma2(O2[i][0], ap, bp[1][0]); ffma2(O2[i][1], ap, bp[1][1]);
                ap = pack2(pa[i].z);
                ffma2(O2[i][0], ap, bp[2][0]); ffma2(O2[i][1], ap, bp[2][1]);
                ap = pack2(pa[i].w);
                ffma2(O2[i][0], ap, bp[3][0]); ffma2(O2[i][1], ap, bp[3][1]);
            }
        }
    }

    const int b = bh >> 4, h = bh & 15;
#pragma unroll
    for (int i = 0; i < 8; i++) {
        float inv = 1.f / l_i[i];
        float o0, o1, o2, o3;
        unpack2(O2[i][0], o0, o1);
        unpack2(O2[i][1], o2, o3);
        int t = q0 + row8 + i;
        float* p = g_y + ((size_t)b * TT + t) * CC + h * DD + col4;
        *(float4*)p = make_float4(o0 * inv, o1 * inv, o2 * inv, o3 * inv);
    }
}

// ---------------------------------------------------------------------------
extern "C" void kernel_launch(void* const* d_in, const int* in_sizes, int n_in,
                              void* d_out, int out_size)
{
    (void)in_sizes; (void)n_in; (void)out_size;
    const float* x      = (const float*)d_in[0];
    const float* W_attn = (const float*)d_in[1];
    const float* b_attn = (const float*)d_in[2];
    const float* W_proj = (const float*)d_in[3];
    const float* b_proj = (const float*)d_in[4];
    float* out = (float*)d_out;

    cudaFuncSetAttribute(attn_kernel,
                         cudaFuncAttributeMaxDynamicSharedMemorySize,
                         ATTN_SMEM_BYTES);

    qkv_p2_kernel <<<dim3(3072 / 128, MROWS / 128), 256>>>(x, W_attn, b_attn);
    // Heavy-first grid: x = bh (64), y = q-block (16, reversed inside kernel).
    attn_kernel   <<<dim3(BB * HH, TT / 128), 256, ATTN_SMEM_BYTES>>>();
    proj_p2_kernel<<<dim3(CC / 128, MROWS / 128), 256>>>(W_proj, b_proj, out);
}

// round 16
// speedup vs baseline: 1.2618x; 1.0371x over previous
#include <cuda_runtime.h>
#include <cstdint>

// Problem constants
#define BB   4
#define TT   2048
#define CC   1024
#define HH   16
#define DD   64
#define MROWS (BB*TT)      // 8192

// Scratch (static device globals — accessed ONLY via symbol inside kernels;
// never passed as kernel arguments from host code).
__device__ float g_q[BB*HH*TT*DD];   // [B,H,T,d]
__device__ float g_k[BB*HH*TT*DD];
__device__ float g_v[BB*HH*TT*DD];
__device__ float g_y[BB*TT*CC];      // attention output, [B,T,C]

// ============================================================================
// Packed f32x2 + cp.async helpers
// ============================================================================
typedef unsigned long long u64;

__device__ __forceinline__ u64 pack2(float x) {
    u64 r;
    asm("mov.b64 %0, {%1, %1};" : "=l"(r) : "f"(x));
    return r;
}
__device__ __forceinline__ void ffma2(u64& d, u64 a, u64 b) {
    asm("fma.rn.f32x2 %0, %1, %2, %0;" : "+l"(d) : "l"(a), "l"(b));
}
__device__ __forceinline__ void fmul2(u64& d, u64 a) {
    asm("mul.rn.f32x2 %0, %0, %1;" : "+l"(d) : "l"(a));
}
__device__ __forceinline__ void unpack2(u64 v, float& lo, float& hi) {
    asm("mov.b64 {%0, %1}, %2;" : "=f"(lo), "=f"(hi) : "l"(v));
}
__device__ __forceinline__ uint32_t smem_u32_of(const void* p) {
    uint32_t a;
    asm("{ .reg .u64 t; cvta.to.shared.u64 t, %1; cvt.u32.u64 %0, t; }"
        : "=r"(a) : "l"(p));
    return a;
}
#define CPG16(dst_sm, src) \
    asm volatile("cp.async.cg.shared.global [%0], [%1], 16;" \
                 :: "r"(dst_sm), "l"(src))
#define CP_COMMIT() asm volatile("cp.async.commit_group;" ::: "memory")
#define CP_WAIT0()  asm volatile("cp.async.wait_group 0;" ::: "memory")

// ============================================================================
// Packed-FMA GEMM, double-buffered, BK=8, 2 CTA/SM (Round-16).
// out[M,N] = A[M,1024] @ W[1024,N] + bias
// CTA 128x128, 256 threads, 8x8/thread (8x4 packed pairs).
// __launch_bounds__(256,2): 128-reg cap; BK=8 keeps staging to 2 float4
// (8 regs) so the whole live set (~110) fits -> 4 warps/SMSP latency cover.
// B half-interleaved: fragment reads conflict-free.
// ============================================================================
__global__ __launch_bounds__(256, 2)
void qkv_p2_kernel(const float* __restrict__ Ag, const float* __restrict__ Wg,
                   const float* __restrict__ bias)
{
    __shared__ float As[2][8][132];   // k-major: As[buf][k][m]
    __shared__ float Bs[2][8][132];   // Bs[buf][k][interleaved n]

    const int tid  = threadIdx.x;
    const int ty   = tid >> 4, tx = tid & 15;
    const int row8 = ty * 8,  col8 = tx * 8;
    const int m0   = blockIdx.y * 128;
    const int n0   = blockIdx.x * 128;

    // Fill mappings: 1 float4 each for A and B per thread per chunk
    const int ar = tid >> 1;                 // A row 0..127
    const int aq = (tid & 1) * 4;            // A k-offset 0 or 4
    const int bk = tid >> 5;                 // B k row 0..7
    const int bc = tid & 31;                 // B physical chunk
    const int bj = (((bc & 15) << 1) | (bc >> 4)) * 4;  // logical col offset

    const float* aptr = Ag + (size_t)(m0 + ar) * 1024 + aq;
    const float* bptr = Wg + (size_t)bk * 3072 + n0 + bj;

    u64 acc2[8][4];
#pragma unroll
    for (int i = 0; i < 8; i++)
#pragma unroll
        for (int j = 0; j < 4; j++) acc2[i][j] = 0ull;

    // Prologue: chunk 0
    float4 av = *(const float4*)aptr;
    float4 bv = *(const float4*)bptr;
    As[0][aq + 0][ar] = av.x; As[0][aq + 1][ar] = av.y;
    As[0][aq + 2][ar] = av.z; As[0][aq + 3][ar] = av.w;
    *(float4*)&Bs[0][bk][4 * bc] = bv;
    __syncthreads();

    for (int s = 0; s < 128; s++) {
        const int buf = s & 1;

        // Prefetch chunk s+1 (LDG issues before compute)
        if (s < 127) {
            av = *(const float4*)(aptr + (s + 1) * 8);
            bv = *(const float4*)(bptr + (size_t)(s + 1) * 8 * 3072);
        }

#pragma unroll
        for (int kk = 0; kk < 8; kk++) {
            float a[8];
            *(float4*)&a[0] = *(float4*)&As[buf][kk][row8];
            *(float4*)&a[4] = *(float4*)&As[buf][kk][row8 + 4];
            float4 b0 = *(float4*)&Bs[buf][kk][4 * tx];        // cols 8tx..+3
            float4 b1 = *(float4*)&Bs[buf][kk][64 + 4 * tx];   // cols 8tx+4..+7
            u64 bp[4];
            bp[0] = ((const u64*)&b0)[0];
            bp[1] = ((const u64*)&b0)[1];
            bp[2] = ((const u64*)&b1)[0];
            bp[3] = ((const u64*)&b1)[1];
#pragma unroll
            for (int i = 0; i < 8; i++) {
                u64 ap = pack2(a[i]);
                ffma2(acc2[i][0], ap, bp[0]);
                ffma2(acc2[i][1], ap, bp[1]);
                ffma2(acc2[i][2], ap, bp[2]);
                ffma2(acc2[i][3], ap, bp[3]);
            }
        }

        if (s < 127) {
            As[buf ^ 1][aq + 0][ar] = av.x; As[buf ^ 1][aq + 1][ar] = av.y;
            As[buf ^ 1][aq + 2][ar] = av.z; As[buf ^ 1][aq + 3][ar] = av.w;
            *(float4*)&Bs[buf ^ 1][bk][4 * bc] = bv;
        }
        __syncthreads();
    }

    // Epilogue: unpack, bias add, scatter to g_q/g_k/g_v
    float bvv[8];
#pragma unroll
    for (int j = 0; j < 8; j++) bvv[j] = bias[n0 + col8 + j];

    int sel = (n0 + col8) >> 10;
    int cc0 = (n0 + col8) & 1023;
    int h   = cc0 >> 6;
    int dd  = cc0 & 63;
    float* dst = (sel == 0) ? g_q : ((sel == 1) ? g_k : g_v);
#pragma unroll
    for (int i = 0; i < 8; i++) {
        float acc[8];
#pragma unroll
        for (int jp = 0; jp < 4; jp++)
            unpack2(acc2[i][jp], acc[2 * jp], acc[2 * jp + 1]);
        int m = m0 + row8 + i;
        int b_ = m >> 11, t = m & 2047;
        float* p = dst + ((size_t)((b_ * HH + h) * TT + t)) * DD + dd;
        *(float4*)p = make_float4(acc[0] + bvv[0], acc[1] + bvv[1],
                                  acc[2] + bvv[2], acc[3] + bvv[3]);
        *(float4*)(p + 4) = make_float4(acc[4] + bvv[4], acc[5] + bvv[5],
                                        acc[6] + bvv[6], acc[7] + bvv[7]);
    }
}

__global__ __launch_bounds__(256, 2)
void proj_p2_kernel(const float* __restrict__ Wg, const float* __restrict__ bias,
                    float* __restrict__ out)
{
    __shared__ float As[2][8][132];
    __shared__ float Bs[2][8][132];

    const int tid  = threadIdx.x;
    const int ty   = tid >> 4, tx = tid & 15;
    const int row8 = ty * 8,  col8 = tx * 8;
    const int m0   = blockIdx.y * 128;
    const int n0   = blockIdx.x * 128;

    const int ar = tid >> 1;
    const int aq = (tid & 1) * 4;
    const int bk = tid >> 5;
    const int bc = tid & 31;
    const int bj = (((bc & 15) << 1) | (bc >> 4)) * 4;

    const float* aptr = g_y + (size_t)(m0 + ar) * 1024 + aq;   // symbol access
    const float* bptr = Wg + (size_t)bk * CC + n0 + bj;

    u64 acc2[8][4];
#pragma unroll
    for (int i = 0; i < 8; i++)
#pragma unroll
        for (int j = 0; j < 4; j++) acc2[i][j] = 0ull;

    float4 av = *(const float4*)aptr;
    float4 bv = *(const float4*)bptr;
    As[0][aq + 0][ar] = av.x; As[0][aq + 1][ar] = av.y;
    As[0][aq + 2][ar] = av.z; As[0][aq + 3][ar] = av.w;
    *(float4*)&Bs[0][bk][4 * bc] = bv;
    __syncthreads();

    for (int s = 0; s < 128; s++) {
        const int buf = s & 1;

        if (s < 127) {
            av = *(const float4*)(aptr + (s + 1) * 8);
            bv = *(const float4*)(bptr + (size_t)(s + 1) * 8 * CC);
        }

#pragma unroll
        for (int kk = 0; kk < 8; kk++) {
            float a[8];
            *(float4*)&a[0] = *(float4*)&As[buf][kk][row8];
            *(float4*)&a[4] = *(float4*)&As[buf][kk][row8 + 4];
            float4 b0 = *(float4*)&Bs[buf][kk][4 * tx];
            float4 b1 = *(float4*)&Bs[buf][kk][64 + 4 * tx];
            u64 bp[4];
            bp[0] = ((const u64*)&b0)[0];
            bp[1] = ((const u64*)&b0)[1];
            bp[2] = ((const u64*)&b1)[0];
            bp[3] = ((const u64*)&b1)[1];
#pragma unroll
            for (int i = 0; i < 8; i++) {
                u64 ap = pack2(a[i]);
                ffma2(acc2[i][0], ap, bp[0]);
                ffma2(acc2[i][1], ap, bp[1]);
                ffma2(acc2[i][2], ap, bp[2]);
                ffma2(acc2[i][3], ap, bp[3]);
            }
        }

        if (s < 127) {
            As[buf ^ 1][aq + 0][ar] = av.x; As[buf ^ 1][aq + 1][ar] = av.y;
            As[buf ^ 1][aq + 2][ar] = av.z; As[buf ^ 1][aq + 3][ar] = av.w;
            *(float4*)&Bs[buf ^ 1][bk][4 * bc] = bv;
        }
        __syncthreads();
    }

    float bvv[8];
#pragma unroll
    for (int j = 0; j < 8; j++) bvv[j] = bias[n0 + col8 + j];
#pragma unroll
    for (int i = 0; i < 8; i++) {
        float acc[8];
#pragma unroll
        for (int jp = 0; jp < 4; jp++)
            unpack2(acc2[i][jp], acc[2 * jp], acc[2 * jp + 1]);
        int m = m0 + row8 + i;
        float* p = out + (size_t)m * CC + n0 + col8;
        *(float4*)p = make_float4(acc[0] + bvv[0], acc[1] + bvv[1],
                                  acc[2] + bvv[2], acc[3] + bvv[3]);
        *(float4*)(p + 4) = make_float4(acc[4] + bvv[4], acc[5] + bvv[5],
                                        acc[6] + bvv[6], acc[7] + bvv[7]);
    }
}

// ---------------------------------------------------------------------------
// Kernel 2: Flash attention — BYTE-IDENTICAL to the Round-15 winner
// (packed f32x2, cp.async V, own Ps buffer, heavy-first grid).
// ---------------------------------------------------------------------------
#define ATTN_SMEM_FLOATS (64*132 + 64*68 + 64*68 + 128*68)
#define ATTN_SMEM_BYTES  (ATTN_SMEM_FLOATS * 4)

__global__ __launch_bounds__(256, 2)
void attn_kernel()
{
    extern __shared__ float smem[];
    float (*Qt)[132] = (float(*)[132])smem;                        // [d][query]
    float (*Kt)[68]  = (float(*)[68])(smem + 64 * 132);            // [d][key]
    float (*Vs)[68]  = (float(*)[68])(smem + 64 * 132 + 64 * 68);  // [key][d]
    float (*Ps)[68]  = (float(*)[68])(smem + 64 * 132 + 2 * 64 * 68); // [q][key]

    const int tid  = threadIdx.x;
    const int ty   = tid >> 4, tx = tid & 15;
    const int row8 = ty * 8;
    const int col4 = tx * 4;

    const int q0 = (gridDim.y - 1 - blockIdx.y) * 128;   // heavy-first
    const int bh = blockIdx.x;        // b*16 + h
    const float* qbase = g_q + ((size_t)bh * TT + q0) * DD;
    const uint32_t vs_base = smem_u32_of(&Vs[0][0]);

    const float scale = 0.125f;
#pragma unroll
    for (int it = 0; it < 8; it++) {
        int idx = tid + 256 * it;
        int r   = idx >> 4;
        int dq  = (idx & 15) * 4;
        float4 v = *(const float4*)(qbase + (size_t)r * DD + dq);
        Qt[dq + 0][r] = v.x * scale; Qt[dq + 1][r] = v.y * scale;
        Qt[dq + 2][r] = v.z * scale; Qt[dq + 3][r] = v.w * scale;
    }

    float m_i[8], l_i[8];
    u64 O2[8][2];
#pragma unroll
    for (int i = 0; i < 8; i++) {
        m_i[i] = -1e30f; l_i[i] = 0.f;
        O2[i][0] = 0ull; O2[i][1] = 0ull;
    }

    const int maskStart = q0 >> 6;
    const int nblk      = maskStart + 2;

    for (int kb = 0; kb < nblk; kb++) {
        __syncthreads();

        {
            const float* vb = g_v + ((size_t)bh * TT + kb * 64) * DD;
#pragma unroll
            for (int it = 0; it < 4; it++) {
                int idx = tid + 256 * it;
                int r   = idx >> 4;
                int dq  = (idx & 15) * 4;
                CPG16(vs_base + (r * 68 + dq) * 4, vb + (size_t)r * DD + dq);
            }
            CP_COMMIT();
        }

        {
            const float* kbase = g_k + ((size_t)bh * TT + kb * 64) * DD;
#pragma unroll
            for (int it = 0; it < 4; it++) {
                int idx = tid + 256 * it;
                int r   = idx >> 4;
                int dq  = (idx & 15) * 4;
                float4 kv = *(const float4*)(kbase + (size_t)r * DD + dq);
                Kt[dq + 0][r] = kv.x; Kt[dq + 1][r] = kv.y;
                Kt[dq + 2][r] = kv.z; Kt[dq + 3][r] = kv.w;
            }
        }
        __syncthreads();

        u64 s2[4][4];
#pragma unroll
        for (int p = 0; p < 4; p++)
#pragma unroll
            for (int j = 0; j < 4; j++) s2[p][j] = 0ull;

#pragma unroll 4
        for (int dd = 0; dd < 64; dd++) {
            float4 a0 = *(float4*)&Qt[dd][row8];
            float4 a1 = *(float4*)&Qt[dd][row8 + 4];
            u64 qp[4];
            qp[0] = ((const u64*)&a0)[0];
            qp[1] = ((const u64*)&a0)[1];
            qp[2] = ((const u64*)&a1)[0];
            qp[3] = ((const u64*)&a1)[1];
            float4 bq = *(float4*)&Kt[dd][col4];
            u64 k0 = pack2(bq.x), k1 = pack2(bq.y),
                k2 = pack2(bq.z), k3 = pack2(bq.w);
#pragma unroll
            for (int p = 0; p < 4; p++) {
                ffma2(s2[p][0], qp[p], k0);
                ffma2(s2[p][1], qp[p], k1);
                ffma2(s2[p][2], qp[p], k2);
                ffma2(s2[p][3], qp[p], k3);
            }
        }

        float s[8][4];
#pragma unroll
        for (int p = 0; p < 4; p++)
#pragma unroll
            for (int j = 0; j < 4; j++)
                unpack2(s2[p][j], s[2 * p][j], s[2 * p + 1][j]);

        if (kb >= maskStart) {
#pragma unroll
            for (int i = 0; i < 8; i++) {
                int gq = q0 + row8 + i;
#pragma unroll
                for (int j = 0; j < 4; j++) {
                    int gk = kb * 64 + col4 + j;
                    if (gk > gq) s[i][j] = -1e30f;
                }
            }
        }

#pragma unroll
        for (int i = 0; i < 8; i++) {
            float v = fmaxf(fmaxf(s[i][0], s[i][1]), fmaxf(s[i][2], s[i][3]));
#pragma unroll
            for (int o = 1; o < 16; o <<= 1)
                v = fmaxf(v, __shfl_xor_sync(0xffffffffu, v, o));
            float mnew  = fmaxf(m_i[i], v);
            float alpha = __expf(m_i[i] - mnew);
            m_i[i] = mnew;
            float ps = 0.f;
#pragma unroll
            for (int j = 0; j < 4; j++) {
                s[i][j] = __expf(s[i][j] - mnew);
                ps += s[i][j];
            }
#pragma unroll
            for (int o = 1; o < 16; o <<= 1)
                ps += __shfl_xor_sync(0xffffffffu, ps, o);
            l_i[i] = l_i[i] * alpha + ps;
            u64 ap = pack2(alpha);
            fmul2(O2[i][0], ap);
            fmul2(O2[i][1], ap);
        }

#pragma unroll
        for (int i = 0; i < 8; i++)
            *(float4*)&Ps[row8 + i][col4] =
                make_float4(s[i][0], s[i][1], s[i][2], s[i][3]);

        CP_WAIT0();
        __syncthreads();

#pragma unroll 2
        for (int j = 0; j < 64; j += 4) {
            float4 pa[8];
#pragma unroll
            for (int i = 0; i < 8; i++) pa[i] = *(float4*)&Ps[row8 + i][j];
            float4 b0 = *(float4*)&Vs[j + 0][col4];
            float4 b1 = *(float4*)&Vs[j + 1][col4];
            float4 b2 = *(float4*)&Vs[j + 2][col4];
            float4 b3 = *(float4*)&Vs[j + 3][col4];
            u64 bp[4][2];
            bp[0][0] = ((const u64*)&b0)[0]; bp[0][1] = ((const u64*)&b0)[1];
            bp[1][0] = ((const u64*)&b1)[0]; bp[1][1] = ((const u64*)&b1)[1];
            bp[2][0] = ((const u64*)&b2)[0]; bp[2][1] = ((const u64*)&b2)[1];
            bp[3][0] = ((const u64*)&b3)[0]; bp[3][1] = ((const u64*)&b3)[1];
#pragma unroll
            for (int i = 0; i < 8; i++) {
                u64 ap;
                ap = pack2(pa[i].x);
                ffma2(O2[i][0], ap, bp[0][0]); ffma2(O2[i][1], ap, bp[0][1]);
                ap = pack2(pa[i].y);
                ffma2(O2[i][0], ap, bp[1][0]); ffma2(O2[i][1], ap, bp[1][1]);
                ap = pack2(pa[i].z);
                ffma2(O2[i][0], ap, bp[2][0]); ffma2(O2[i][1], ap, bp[2][1]);
                ap = pack2(pa[i].w);
                ffma2(O2[i][0], ap, bp[3][0]); ffma2(O2[i][1], ap, bp[3][1]);
            }
        }
    }

    const int b = bh >> 4, h = bh & 15;
#pragma unroll
    for (int i = 0; i < 8; i++) {
        float inv = 1.f / l_i[i];
        float o0, o1, o2, o3;
        unpack2(O2[i][0], o0, o1);
        unpack2(O2[i][1], o2, o3);
        int t = q0 + row8 + i;
        float* p = g_y + ((size_t)b * TT + t) * CC + h * DD + col4;
        *(float4*)p = make_float4(o0 * inv, o1 * inv, o2 * inv, o3 * inv);
    }
}

// ---------------------------------------------------------------------------
extern "C" void kernel_launch(void* const* d_in, const int* in_sizes, int n_in,
                              void* d_out, int out_size)
{
    (void)in_sizes; (void)n_in; (void)out_size;
    const float* x      = (const float*)d_in[0];
    const float* W_attn = (const float*)d_in[1];
    const float* b_attn = (const float*)d_in[2];
    const float* W_proj = (const float*)d_in[3];
    const float* b_proj = (const float*)d_in[4];
    float* out = (float*)d_out;

    cudaFuncSetAttribute(attn_kernel,
                         cudaFuncAttributeMaxDynamicSharedMemorySize,
                         ATTN_SMEM_BYTES);

    qkv_p2_kernel <<<dim3(3072 / 128, MROWS / 128), 256>>>(x, W_attn, b_attn);
    attn_kernel   <<<dim3(BB * HH, TT / 128), 256, ATTN_SMEM_BYTES>>>();
    proj_p2_kernel<<<dim3(CC / 128, MROWS / 128), 256>>>(W_proj, b_proj, out);
}